// round 1
// baseline (speedup 1.0000x reference)
#include <cuda_runtime.h>
#include <cuda_bf16.h>
#include <math.h>

// Problem constants (fixed by the dataset)
#define BB 2048
#define TT 200
#define EE 64
#define HH 128
#define TP 201   // padded T stride for h_e smem (odd -> conflict-free)

// Pure-FMA sigmoid: exp2 via degree-7 poly + exponent bit-trick, Newton rcp.
// Zero MUFU (MUFU rt=8/SMSP would bottleneck at 9.8M sigmoids).
__device__ __forceinline__ float sigmoid_sw(float x) {
    float ax = fminf(fabsf(x), 87.0f);
    float t  = ax * -1.4426950408889634f;     // t in [-125.5, 0]
    float fi = floorf(t);
    float f  = t - fi;                        // [0,1)
    float p  = 1.5252733804059837e-5f;
    p = fmaf(p, f, 1.5403530167651635e-4f);
    p = fmaf(p, f, 1.3333558146428443e-3f);
    p = fmaf(p, f, 9.6181291076284771e-3f);
    p = fmaf(p, f, 5.5504108664821580e-2f);
    p = fmaf(p, f, 2.4022650695910071e-1f);
    p = fmaf(p, f, 6.9314718055994531e-1f);
    p = fmaf(p, f, 1.0f);
    int ei = (int)fi;                         // [-126, 0]
    float sc = __int_as_float((ei + 127) << 23);
    float e  = p * sc;                        // exp(-|x|) in (0,1]
    float d  = 1.0f + e;                      // (1,2]
    float r  = fmaf(-0.5f, d, 1.4571067811865475f);  // linear minimax seed for 1/d
    r = r * fmaf(-d, r, 2.0f);                // Newton 1
    r = r * fmaf(-d, r, 2.0f);                // Newton 2  (rel err ~5e-5)
    return (x >= 0.0f) ? r : e * r;           // sigmoid(-a) = e/(1+e)
}

// SMEM layout (floats)
#define OFF_Q      0        // 128
#define OFF_W      128      // 2048   W_eff[k][j], j contiguous
#define OFF_CB     2176     // 16
#define OFF_AW2    2192     // 128
#define OFF_AB2    2320     // 8
#define OFF_AW3    2328     // 8
#define OFF_MISC   2336     // 8: [0]=ab3 [1]=max [2]=inv_sum [3]=out_scalar
#define OFF_SC     2344     // 208 (scores/att)
#define OFF_RED    2552     // 256
#define OFF_H1     2808     // 128
#define OFF_H2     2936     // 128
#define OFF_DIN    3064     // 256
#define OFF_S1     3320     // 16
#define OFF_S2     3336     // 8
#define OFF_HID    3344     // 200 ints
#define OFF_H      3552     // 128*201 = 25728
#define SMEM_FLOATS (OFF_H + 128 * TP)
#define SMEM_BYTES  (SMEM_FLOATS * 4)

__global__ void __launch_bounds__(256, 1) din_kernel(
    const int* __restrict__ iidx, const int* __restrict__ hist_i,
    const int* __restrict__ sl, const int* __restrict__ category_list,
    const float* __restrict__ item_emb, const float* __restrict__ cat_emb,
    const float* __restrict__ item_b,
    const float* __restrict__ aw1, const float* __restrict__ ab1,
    const float* __restrict__ aw2, const float* __restrict__ ab2,
    const float* __restrict__ aw3, const float* __restrict__ ab3,
    const float* __restrict__ aw4, const float* __restrict__ ab4,
    const float* __restrict__ bn_gamma, const float* __restrict__ bn_beta,
    const float* __restrict__ bn_mean, const float* __restrict__ bn_var,
    const float* __restrict__ w1, const float* __restrict__ b1,
    const float* __restrict__ w2, const float* __restrict__ b2,
    const float* __restrict__ w3, const float* __restrict__ b3,
    float* __restrict__ out)
{
    extern __shared__ float sm[];
    float* q    = sm + OFF_Q;
    float* W    = sm + OFF_W;
    float* cb   = sm + OFF_CB;
    float* aw2s = sm + OFF_AW2;
    float* ab2s = sm + OFF_AB2;
    float* aw3s = sm + OFF_AW3;
    float* misc = sm + OFF_MISC;
    float* sc   = sm + OFF_SC;
    float* red  = sm + OFF_RED;
    float* h1   = sm + OFF_H1;
    float* h2   = sm + OFF_H2;
    float* din  = sm + OFF_DIN;
    float* s1   = sm + OFF_S1;
    float* s2   = sm + OFF_S2;
    int*   hid  = (int*)(sm + OFF_HID);
    float* h    = sm + OFF_H;

    const int b   = blockIdx.x;
    const int tid = threadIdx.x;

    const int ib  = iidx[b];
    const int icat = category_list[ib];
    const int slb = sl[b];

    // ---- phase 0: load q (i_e), hist indices, small consts ----
    if (tid < 128)
        q[tid] = (tid < 64) ? item_emb[(size_t)ib * EE + tid]
                            : cat_emb[(size_t)icat * EE + (tid - 64)];
    if (tid < TT) hid[tid] = hist_i[b * TT + tid];
    if (tid < 128) aw2s[tid] = aw2[tid];
    if (tid < 8) { ab2s[tid] = ab2[tid]; aw3s[tid] = aw3[tid]; }
    if (tid == 0) misc[0] = ab3[0];
    __syncthreads();

    // ---- phase 1: W_eff[k][j] = (A2-A3)[k][j] + q[k]*A4[k][j]; cb partials ----
    {
        int base = tid * 8;               // 2048 elems / 256 thr
        int k  = base >> 4;
        int j0 = base & 15;
        float qk = q[k];
        #pragma unroll
        for (int r = 0; r < 8; r++) {
            int j = j0 + r;
            W[k * 16 + j] = aw1[(128 + k) * 16 + j] - aw1[(256 + k) * 16 + j]
                          + qk * aw1[(384 + k) * 16 + j];
        }
        int jj = tid & 15, ch = tid >> 4;     // 16 chunks of 8 k's
        float p = 0.0f;
        #pragma unroll
        for (int r = 0; r < 8; r++) {
            int kk = ch * 8 + r;
            p += q[kk] * (aw1[kk * 16 + jj] + aw1[(256 + kk) * 16 + jj]);
        }
        red[ch * 16 + jj] = p;
    }
    __syncthreads();
    if (tid < 16) {
        float s = ab1[tid];
        #pragma unroll
        for (int ch = 0; ch < 16; ch++) s += red[ch * 16 + tid];
        cb[tid] = s;
    }

    // ---- phase 2a: stage h_e transposed into smem: h[k*TP + t] ----
    if (tid < TT) {
        int hd = hid[tid];
        const float4* irow = (const float4*)item_emb + (size_t)hd * 16;
        const float4* crow = (const float4*)cat_emb + (size_t)hd * 16;
        #pragma unroll
        for (int qd = 0; qd < 16; qd++) {
            float4 v = irow[qd];
            int k0 = qd * 4;
            h[(k0 + 0) * TP + tid] = v.x; h[(k0 + 1) * TP + tid] = v.y;
            h[(k0 + 2) * TP + tid] = v.z; h[(k0 + 3) * TP + tid] = v.w;
        }
        #pragma unroll
        for (int qd = 0; qd < 16; qd++) {
            float4 v = crow[qd];
            int k0 = 64 + qd * 4;
            h[(k0 + 0) * TP + tid] = v.x; h[(k0 + 1) * TP + tid] = v.y;
            h[(k0 + 2) * TP + tid] = v.z; h[(k0 + 3) * TP + tid] = v.w;
        }
    }
    __syncthreads();

    // ---- phase 2b: per-t attention MLP -> raw masked scores ----
    if (tid < TT) {
        float acc[16];
        #pragma unroll
        for (int j = 0; j < 16; j++) acc[j] = cb[j];
        const float4* W4 = (const float4*)W;
        #pragma unroll 4
        for (int k = 0; k < 128; k++) {
            float hv = h[k * TP + tid];
            float4 w0 = W4[k * 4 + 0];
            float4 w1v = W4[k * 4 + 1];
            float4 w2v = W4[k * 4 + 2];
            float4 w3v = W4[k * 4 + 3];
            acc[0]  = fmaf(hv, w0.x,  acc[0]);  acc[1]  = fmaf(hv, w0.y,  acc[1]);
            acc[2]  = fmaf(hv, w0.z,  acc[2]);  acc[3]  = fmaf(hv, w0.w,  acc[3]);
            acc[4]  = fmaf(hv, w1v.x, acc[4]);  acc[5]  = fmaf(hv, w1v.y, acc[5]);
            acc[6]  = fmaf(hv, w1v.z, acc[6]);  acc[7]  = fmaf(hv, w1v.w, acc[7]);
            acc[8]  = fmaf(hv, w2v.x, acc[8]);  acc[9]  = fmaf(hv, w2v.y, acc[9]);
            acc[10] = fmaf(hv, w2v.z, acc[10]); acc[11] = fmaf(hv, w2v.w, acc[11]);
            acc[12] = fmaf(hv, w3v.x, acc[12]); acc[13] = fmaf(hv, w3v.y, acc[13]);
            acc[14] = fmaf(hv, w3v.z, acc[14]); acc[15] = fmaf(hv, w3v.w, acc[15]);
        }
        float x1[16];
        #pragma unroll
        for (int j = 0; j < 16; j++) x1[j] = sigmoid_sw(acc[j]);
        float y[8];
        #pragma unroll
        for (int o = 0; o < 8; o++) y[o] = ab2s[o];
        #pragma unroll
        for (int j = 0; j < 16; j++) {
            float xv = x1[j];
            #pragma unroll
            for (int o = 0; o < 8; o++) y[o] = fmaf(xv, aw2s[j * 8 + o], y[o]);
        }
        float s = misc[0];
        #pragma unroll
        for (int o = 0; o < 8; o++) s = fmaf(sigmoid_sw(y[o]), aw3s[o], s);
        if (tid >= slb) s = -4294967295.0f;        // -(2^32 - 1)
        sc[tid] = s * 0.08838834764831844f;        // / sqrt(128)
    }
    __syncthreads();

    // ---- phase 2c: softmax over T ----
    if (tid < 32) {
        float m = -INFINITY;
        for (int t = tid; t < TT; t += 32) m = fmaxf(m, sc[t]);
        #pragma unroll
        for (int o = 16; o; o >>= 1) m = fmaxf(m, __shfl_xor_sync(0xffffffffu, m, o));
        if (tid == 0) misc[1] = m;
    }
    __syncthreads();
    if (tid < TT) sc[tid] = __expf(sc[tid] - misc[1]);
    __syncthreads();
    if (tid < 32) {
        float sv = 0.0f;
        for (int t = tid; t < TT; t += 32) sv += sc[t];
        #pragma unroll
        for (int o = 16; o; o >>= 1) sv += __shfl_xor_sync(0xffffffffu, sv, o);
        if (tid == 0) misc[2] = 1.0f / sv;
    }
    __syncthreads();

    // ---- phase 3a: hist[k] = inv_sum * sum_t sc[t]*h[k][t] ----
    {
        int k = tid & 127, hf = tid >> 7;
        float a = 0.0f;
        int t0 = hf * 100;
        for (int t = t0; t < t0 + 100; t++) a = fmaf(sc[t], h[k * TP + t], a);
        red[tid] = a;
    }
    __syncthreads();
    if (tid < 128) h1[tid] = (red[tid] + red[tid + 128]) * misc[2];
    __syncthreads();

    // ---- phase 3b: hist @ aw4 + ab4 ----
    if (tid < 128) {
        float a = ab4[tid];
        for (int k = 0; k < 128; k++) a = fmaf(h1[k], aw4[k * 128 + tid], a);
        h2[tid] = a;
    }
    __syncthreads();

    // ---- phase 4: BN + head MLP (linear) ----
    {
        float v = (tid < 128) ? h2[tid] : q[tid - 128];
        float inv = rsqrtf(bn_var[tid] + 1e-3f);
        din[tid] = fmaf((v - bn_mean[tid]) * inv, bn_gamma[tid], bn_beta[tid]);
    }
    __syncthreads();
    if (tid < 16) {
        float a = b1[tid];
        for (int m = 0; m < 256; m++) a = fmaf(din[m], w1[m * 16 + tid], a);
        s1[tid] = a;
    }
    __syncthreads();
    if (tid < 8) {
        float a = b2[tid];
        #pragma unroll
        for (int j = 0; j < 16; j++) a = fmaf(s1[j], w2[j * 8 + tid], a);
        s2[tid] = a;
    }
    __syncthreads();
    if (tid == 0) {
        float a = b3[0];
        #pragma unroll
        for (int o = 0; o < 8; o++) a = fmaf(s2[o], w3[o], a);
        misc[3] = a;
    }
    __syncthreads();

    // ---- epilogue: out[b][c] = out_scalar[b] + item_b[i[c]] ----
    float s3 = misc[3];
    for (int c = tid; c < BB; c += 256) {
        out[(size_t)b * BB + c] = s3 + item_b[iidx[c]];
    }
}

extern "C" void kernel_launch(void* const* d_in, const int* in_sizes, int n_in,
                              void* d_out, int out_size) {
    const int*   i_arr   = (const int*)d_in[1];
    const int*   hist_i  = (const int*)d_in[2];
    const int*   sl      = (const int*)d_in[3];
    const int*   catlist = (const int*)d_in[4];
    const float* item_emb = (const float*)d_in[5];
    const float* cat_emb  = (const float*)d_in[6];
    const float* item_b   = (const float*)d_in[7];
    const float* aw1 = (const float*)d_in[8];
    const float* ab1 = (const float*)d_in[9];
    const float* aw2 = (const float*)d_in[10];
    const float* ab2 = (const float*)d_in[11];
    const float* aw3 = (const float*)d_in[12];
    const float* ab3 = (const float*)d_in[13];
    const float* aw4 = (const float*)d_in[14];
    const float* ab4 = (const float*)d_in[15];
    const float* bn_gamma = (const float*)d_in[16];
    const float* bn_beta  = (const float*)d_in[17];
    const float* bn_mean  = (const float*)d_in[18];
    const float* bn_var   = (const float*)d_in[19];
    const float* w1 = (const float*)d_in[20];
    const float* b1 = (const float*)d_in[21];
    const float* w2 = (const float*)d_in[22];
    const float* b2 = (const float*)d_in[23];
    const float* w3 = (const float*)d_in[24];
    const float* b3 = (const float*)d_in[25];
    float* out = (float*)d_out;

    cudaFuncSetAttribute(din_kernel,
                         cudaFuncAttributeMaxDynamicSharedMemorySize, SMEM_BYTES);

    const int B = in_sizes[1];   // 2048
    din_kernel<<<B, 256, SMEM_BYTES>>>(
        i_arr, hist_i, sl, catlist, item_emb, cat_emb, item_b,
        aw1, ab1, aw2, ab2, aw3, ab3, aw4, ab4,
        bn_gamma, bn_beta, bn_mean, bn_var,
        w1, b1, w2, b2, w3, b3, out);
}

// round 2
// speedup vs baseline: 1.3898x; 1.3898x over previous
#include <cuda_runtime.h>
#include <cuda_bf16.h>
#include <math.h>

#define BB 2048
#define TT 200
#define EE 64

__device__ float g_ibg[BB];      // item_b[i[c]] precomputed
__device__ float g_scalar[BB];   // per-b MLP output scalar

// Packed dual-FMA (sm_100+): d.lo += a.lo*b.lo, d.hi += a.hi*b.hi
__device__ __forceinline__ void ffma2(unsigned long long& d,
                                      unsigned long long a,
                                      unsigned long long b) {
    asm("fma.rn.f32x2 %0, %1, %2, %0;" : "+l"(d) : "l"(a), "l"(b));
}

// Pure-FMA sigmoid (no MUFU): exp2 poly + bit-trick + Newton rcp. rel err ~5e-5.
__device__ __forceinline__ float sigmoid_sw(float x) {
    float ax = fminf(fabsf(x), 87.0f);
    float t  = ax * -1.4426950408889634f;
    float fi = floorf(t);
    float f  = t - fi;
    float p  = 1.5252733804059837e-5f;
    p = fmaf(p, f, 1.5403530167651635e-4f);
    p = fmaf(p, f, 1.3333558146428443e-3f);
    p = fmaf(p, f, 9.6181291076284771e-3f);
    p = fmaf(p, f, 5.5504108664821580e-2f);
    p = fmaf(p, f, 2.4022650695910071e-1f);
    p = fmaf(p, f, 6.9314718055994531e-1f);
    p = fmaf(p, f, 1.0f);
    int ei = (int)fi;
    float sc = __int_as_float((ei + 127) << 23);
    float e  = p * sc;
    float d  = 1.0f + e;
    float r  = fmaf(-0.5f, d, 1.4571067811865475f);
    r = r * fmaf(-d, r, 2.0f);
    r = r * fmaf(-d, r, 2.0f);
    return (x >= 0.0f) ? r : e * r;
}

struct SmemT {
    unsigned long long wp[1024];  // W_eff paired: wp[kp*16+j] = (W[2kp][j], W[2kp+1][j])
    float q[128];
    float cb[16];
    float aw2s[128];
    float ab2s[8];
    float aw3s[8];
    float misc[8];     // [0]=ab3 [1]=max [2]=inv_sum
    float sc[200];
    float red[512];
    float h1[128];
    float h2[128];
    float din[256];
    float s1[16];
    float s2[8];
    int   hid[200];
};

__global__ void precompute_kernel(const int* __restrict__ iidx,
                                  const float* __restrict__ item_b) {
    int c = blockIdx.x * 256 + threadIdx.x;
    if (c < BB) g_ibg[c] = item_b[iidx[c]];
}

__global__ void __launch_bounds__(128, 4) din_main(
    const int* __restrict__ iidx, const int* __restrict__ hist_i,
    const int* __restrict__ sl, const int* __restrict__ category_list,
    const float* __restrict__ item_emb, const float* __restrict__ cat_emb,
    const float* __restrict__ aw1, const float* __restrict__ ab1,
    const float* __restrict__ aw2, const float* __restrict__ ab2,
    const float* __restrict__ aw3, const float* __restrict__ ab3,
    const float* __restrict__ aw4, const float* __restrict__ ab4,
    const float* __restrict__ bn_gamma, const float* __restrict__ bn_beta,
    const float* __restrict__ bn_mean, const float* __restrict__ bn_var,
    const float* __restrict__ w1, const float* __restrict__ b1,
    const float* __restrict__ w2, const float* __restrict__ b2,
    const float* __restrict__ w3, const float* __restrict__ b3)
{
    __shared__ SmemT s;
    const int b   = blockIdx.x;
    const int tid = threadIdx.x;

    const int ib   = iidx[b];
    const int icat = category_list[ib];
    const int slb  = sl[b];

    // ---- phase 0: q, hist indices, small consts ----
    s.q[tid] = (tid < 64) ? item_emb[(size_t)ib * EE + tid]
                          : cat_emb[(size_t)icat * EE + (tid - 64)];
    for (int t = tid; t < TT; t += 128) s.hid[t] = hist_i[b * TT + t];
    s.aw2s[tid] = aw2[tid];
    if (tid < 8) { s.ab2s[tid] = ab2[tid]; s.aw3s[tid] = aw3[tid]; }
    if (tid == 0) s.misc[0] = ab3[0];
    __syncthreads();

    // ---- phase 1: paired W_eff + cb ----
    #pragma unroll
    for (int e = tid; e < 1024; e += 128) {
        int kp = e >> 4, j = e & 15;
        int k0 = kp * 2, k1 = k0 + 1;
        float w0 = aw1[(128 + k0) * 16 + j] - aw1[(256 + k0) * 16 + j]
                 + s.q[k0] * aw1[(384 + k0) * 16 + j];
        float w1v = aw1[(128 + k1) * 16 + j] - aw1[(256 + k1) * 16 + j]
                  + s.q[k1] * aw1[(384 + k1) * 16 + j];
        unsigned long long pk = ((unsigned long long)__float_as_uint(w1v) << 32)
                              | (unsigned long long)__float_as_uint(w0);
        s.wp[e] = pk;
    }
    {
        int j = tid & 15, ch = tid >> 4;   // 8 chunks of 16 k
        float p = 0.0f;
        #pragma unroll
        for (int r = 0; r < 16; r++) {
            int k = ch * 16 + r;
            p += s.q[k] * (aw1[k * 16 + j] + aw1[(256 + k) * 16 + j]);
        }
        s.red[ch * 16 + j] = p;
    }
    __syncthreads();
    if (tid < 16) {
        float a = ab1[tid];
        #pragma unroll
        for (int ch = 0; ch < 8; ch++) a += s.red[ch * 16 + tid];
        s.cb[tid] = a;
    }
    __syncthreads();

    // ---- phase 2: attention MLP scores, 2 timesteps per thread ----
    if (tid < 100) {
        const int t0 = tid, t1 = tid + 100;
        int hd0 = s.hid[t0], hd1 = s.hid[t1];
        const ulonglong2* r0i = (const ulonglong2*)(item_emb + (size_t)hd0 * EE);
        const ulonglong2* r0c = (const ulonglong2*)(cat_emb  + (size_t)hd0 * EE);
        const ulonglong2* r1i = (const ulonglong2*)(item_emb + (size_t)hd1 * EE);
        const ulonglong2* r1c = (const ulonglong2*)(cat_emb  + (size_t)hd1 * EE);

        unsigned long long acc0[16], acc1[16];
        #pragma unroll
        for (int j = 0; j < 16; j++) {
            unsigned long long ini = (unsigned long long)__float_as_uint(s.cb[j]);
            acc0[j] = ini; acc1[j] = ini;
        }
        const ulonglong2* wv = (const ulonglong2*)s.wp;

        #pragma unroll 1
        for (int half = 0; half < 2; half++) {
            const ulonglong2* pa = half ? r0c : r0i;
            const ulonglong2* pb = half ? r1c : r1i;
            int kpBase = half * 32;
            #pragma unroll 2
            for (int c = 0; c < 16; c++) {
                ulonglong2 ha = pa[c];
                ulonglong2 hb = pb[c];
                const ulonglong2* w0 = wv + (size_t)(kpBase + 2 * c) * 8;
                const ulonglong2* w1r = w0 + 8;
                #pragma unroll
                for (int p = 0; p < 8; p++) {
                    ulonglong2 wa = w0[p];
                    ffma2(acc0[2 * p],     ha.x, wa.x);
                    ffma2(acc0[2 * p + 1], ha.x, wa.y);
                    ffma2(acc1[2 * p],     hb.x, wa.x);
                    ffma2(acc1[2 * p + 1], hb.x, wa.y);
                }
                #pragma unroll
                for (int p = 0; p < 8; p++) {
                    ulonglong2 wb = w1r[p];
                    ffma2(acc0[2 * p],     ha.y, wb.x);
                    ffma2(acc0[2 * p + 1], ha.y, wb.y);
                    ffma2(acc1[2 * p],     hb.y, wb.x);
                    ffma2(acc1[2 * p + 1], hb.y, wb.y);
                }
            }
        }

        #pragma unroll 1
        for (int pass = 0; pass < 2; pass++) {
            unsigned long long* acc = pass ? acc1 : acc0;
            float x1[16];
            #pragma unroll
            for (int j = 0; j < 16; j++) {
                float lo = __uint_as_float((unsigned)acc[j]);
                float hi = __uint_as_float((unsigned)(acc[j] >> 32));
                x1[j] = sigmoid_sw(lo + hi);
            }
            float y[8];
            #pragma unroll
            for (int o = 0; o < 8; o++) y[o] = s.ab2s[o];
            #pragma unroll
            for (int j = 0; j < 16; j++) {
                float xv = x1[j];
                #pragma unroll
                for (int o = 0; o < 8; o++) y[o] = fmaf(xv, s.aw2s[j * 8 + o], y[o]);
            }
            float sv = s.misc[0];
            #pragma unroll
            for (int o = 0; o < 8; o++) sv = fmaf(sigmoid_sw(y[o]), s.aw3s[o], sv);
            int t = pass ? t1 : t0;
            if (t >= slb) sv = -4294967295.0f;
            s.sc[t] = sv * 0.08838834764831844f;   // / sqrt(128)
        }
    }
    __syncthreads();

    // ---- softmax over T ----
    if (tid < 32) {
        float m = -INFINITY;
        for (int t = tid; t < TT; t += 32) m = fmaxf(m, s.sc[t]);
        #pragma unroll
        for (int o = 16; o; o >>= 1) m = fmaxf(m, __shfl_xor_sync(0xffffffffu, m, o));
        if (tid == 0) s.misc[1] = m;
    }
    __syncthreads();
    for (int t = tid; t < TT; t += 128) s.sc[t] = __expf(s.sc[t] - s.misc[1]);
    __syncthreads();
    if (tid < 32) {
        float sv = 0.0f;
        for (int t = tid; t < TT; t += 32) sv += s.sc[t];
        #pragma unroll
        for (int o = 16; o; o >>= 1) sv += __shfl_xor_sync(0xffffffffu, sv, o);
        if (tid == 0) s.misc[2] = 1.0f / sv;
    }
    __syncthreads();

    // ---- phase 3a: hist[k] = inv * sum_t att[t]*h[t][k] (re-gather from L2) ----
    {
        int w = tid >> 5, l = tid & 31;
        const float* base = (l < 16) ? item_emb : cat_emb;
        int off = (l < 16 ? l : l - 16) * 4;
        int kbase = (l < 16) ? 4 * l : 64 + 4 * (l - 16);
        float a0 = 0.f, a1 = 0.f, a2 = 0.f, a3 = 0.f;
        int tb = w * 50;
        #pragma unroll 2
        for (int tt = tb; tt < tb + 50; tt++) {
            int hd = s.hid[tt];
            float at = s.sc[tt];
            float4 v = *(const float4*)(base + (size_t)hd * EE + off);
            a0 = fmaf(at, v.x, a0); a1 = fmaf(at, v.y, a1);
            a2 = fmaf(at, v.z, a2); a3 = fmaf(at, v.w, a3);
        }
        s.red[w * 128 + kbase + 0] = a0;
        s.red[w * 128 + kbase + 1] = a1;
        s.red[w * 128 + kbase + 2] = a2;
        s.red[w * 128 + kbase + 3] = a3;
    }
    __syncthreads();
    s.h1[tid] = (s.red[tid] + s.red[128 + tid] + s.red[256 + tid] + s.red[384 + tid])
              * s.misc[2];
    __syncthreads();

    // ---- phase 3b: hist @ aw4 + ab4 ----
    {
        float a0 = 0.f, a1 = 0.f;
        #pragma unroll 4
        for (int k = 0; k < 128; k += 2) {
            a0 = fmaf(s.h1[k],     aw4[k * 128 + tid],       a0);
            a1 = fmaf(s.h1[k + 1], aw4[(k + 1) * 128 + tid], a1);
        }
        s.h2[tid] = a0 + a1 + ab4[tid];
    }
    __syncthreads();

    // ---- phase 4: BN + head MLP (all linear) ----
    #pragma unroll
    for (int d = tid; d < 256; d += 128) {
        float v = (d < 128) ? s.h2[d] : s.q[d - 128];
        float inv = rsqrtf(bn_var[d] + 1e-3f);
        s.din[d] = fmaf((v - bn_mean[d]) * inv, bn_gamma[d], bn_beta[d]);
    }
    __syncthreads();
    {
        int j = tid & 15, ch = tid >> 4;  // 8 chunks x 32 m
        float p = 0.0f;
        #pragma unroll
        for (int r = 0; r < 32; r++) {
            int m = ch * 32 + r;
            p = fmaf(s.din[m], w1[m * 16 + j], p);
        }
        s.red[ch * 16 + j] = p;
    }
    __syncthreads();
    if (tid < 16) {
        float a = b1[tid];
        #pragma unroll
        for (int ch = 0; ch < 8; ch++) a += s.red[ch * 16 + tid];
        s.s1[tid] = a;
    }
    __syncthreads();
    if (tid < 8) {
        float a = b2[tid];
        #pragma unroll
        for (int j = 0; j < 16; j++) a = fmaf(s.s1[j], w2[j * 8 + tid], a);
        s.s2[tid] = a;
    }
    __syncthreads();
    if (tid == 0) {
        float a = b3[0];
        #pragma unroll
        for (int o = 0; o < 8; o++) a = fmaf(s.s2[o], w3[o], a);
        g_scalar[b] = a;
    }
}

__global__ void epilogue_kernel(float* __restrict__ out) {
    int b = blockIdx.x;
    float sv = g_scalar[b];
    const float4* g4 = (const float4*)g_ibg;
    float4* o4 = (float4*)(out + (size_t)b * BB);
    #pragma unroll
    for (int c = threadIdx.x; c < BB / 4; c += 128) {
        float4 v = g4[c];
        v.x += sv; v.y += sv; v.z += sv; v.w += sv;
        o4[c] = v;
    }
}

extern "C" void kernel_launch(void* const* d_in, const int* in_sizes, int n_in,
                              void* d_out, int out_size) {
    const int*   i_arr   = (const int*)d_in[1];
    const int*   hist_i  = (const int*)d_in[2];
    const int*   sl      = (const int*)d_in[3];
    const int*   catlist = (const int*)d_in[4];
    const float* item_emb = (const float*)d_in[5];
    const float* cat_emb  = (const float*)d_in[6];
    const float* item_b   = (const float*)d_in[7];
    const float* aw1 = (const float*)d_in[8];
    const float* ab1 = (const float*)d_in[9];
    const float* aw2 = (const float*)d_in[10];
    const float* ab2 = (const float*)d_in[11];
    const float* aw3 = (const float*)d_in[12];
    const float* ab3 = (const float*)d_in[13];
    const float* aw4 = (const float*)d_in[14];
    const float* ab4 = (const float*)d_in[15];
    const float* bn_gamma = (const float*)d_in[16];
    const float* bn_beta  = (const float*)d_in[17];
    const float* bn_mean  = (const float*)d_in[18];
    const float* bn_var   = (const float*)d_in[19];
    const float* w1 = (const float*)d_in[20];
    const float* b1 = (const float*)d_in[21];
    const float* w2 = (const float*)d_in[22];
    const float* b2 = (const float*)d_in[23];
    const float* w3 = (const float*)d_in[24];
    const float* b3 = (const float*)d_in[25];
    float* out = (float*)d_out;

    precompute_kernel<<<(BB + 255) / 256, 256>>>(i_arr, item_b);
    din_main<<<BB, 128>>>(
        i_arr, hist_i, sl, catlist, item_emb, cat_emb,
        aw1, ab1, aw2, ab2, aw3, ab3, aw4, ab4,
        bn_gamma, bn_beta, bn_mean, bn_var,
        w1, b1, w2, b2, w3, b3);
    epilogue_kernel<<<BB, 128>>>(out);
}

// round 3
// speedup vs baseline: 1.8613x; 1.3392x over previous
#include <cuda_runtime.h>
#include <cuda_bf16.h>
#include <math.h>

#define BB 2048
#define TT 200
#define EE 64
#define TC 100      // timestep chunk
#define HPS 101     // hp stride (TC+1)

// ---- persistent device scratch (b-invariant precompute) ----
__device__ float              g_ibg[BB];     // item_b[i[c]]
__device__ unsigned long long g_DP[1024];    // (A2-A3) paired  [kp*16+j]
__device__ unsigned long long g_AP[1024];    // A4 paired       [kp*16+j]
__device__ float              g_S[2048];     // A1+A3           [k*16+j]
__device__ float              g_w1g[4096];   // BN-folded w1    [d*16+j]
__device__ float              g_b1p[16];     // BN-folded b1

__device__ __forceinline__ void ffma2(unsigned long long& d,
                                      unsigned long long a,
                                      unsigned long long b) {
    asm("fma.rn.f32x2 %0, %1, %2, %0;" : "+l"(d) : "l"(a), "l"(b));
}
__device__ __forceinline__ unsigned long long pack2(float lo, float hi) {
    unsigned long long r;
    asm("mov.b64 %0, {%1, %2};" : "=l"(r) : "f"(lo), "f"(hi));
    return r;
}
__device__ __forceinline__ void unpack2(unsigned long long v, float& lo, float& hi) {
    asm("mov.b64 {%0, %1}, %2;" : "=f"(lo), "=f"(hi) : "l"(v));
}

// Pure-FMA sigmoid (no MUFU). rel err ~5e-5.
__device__ __forceinline__ float sigmoid_sw(float x) {
    float ax = fminf(fabsf(x), 87.0f);
    float t  = ax * -1.4426950408889634f;
    float fi = floorf(t);
    float f  = t - fi;
    float p  = 1.5252733804059837e-5f;
    p = fmaf(p, f, 1.5403530167651635e-4f);
    p = fmaf(p, f, 1.3333558146428443e-3f);
    p = fmaf(p, f, 9.6181291076284771e-3f);
    p = fmaf(p, f, 5.5504108664821580e-2f);
    p = fmaf(p, f, 2.4022650695910071e-1f);
    p = fmaf(p, f, 6.9314718055994531e-1f);
    p = fmaf(p, f, 1.0f);
    int ei = (int)fi;
    float sc = __int_as_float((ei + 127) << 23);
    float e  = p * sc;
    float d  = 1.0f + e;
    float r  = fmaf(-0.5f, d, 1.4571067811865475f);
    r = r * fmaf(-d, r, 2.0f);
    r = r * fmaf(-d, r, 2.0f);
    return (x >= 0.0f) ? r : e * r;
}

// ---- K0: b-invariant precompute ----
__global__ void k0_kernel(const int* __restrict__ iidx, const float* __restrict__ item_b,
                          const float* __restrict__ aw1,
                          const float* __restrict__ bn_gamma, const float* __restrict__ bn_beta,
                          const float* __restrict__ bn_mean, const float* __restrict__ bn_var,
                          const float* __restrict__ w1, const float* __restrict__ b1) {
    int blk = blockIdx.x, tid = threadIdx.x;
    if (blk < 8) {
        int c = blk * 256 + tid;
        g_ibg[c] = item_b[iidx[c]];
    } else if (blk == 8) {
        for (int e = tid; e < 1024; e += 256) {
            int kp = e >> 4, j = e & 15;
            int k0 = 2 * kp, k1 = k0 + 1;
            float d0 = aw1[(128 + k0) * 16 + j] - aw1[(256 + k0) * 16 + j];
            float d1 = aw1[(128 + k1) * 16 + j] - aw1[(256 + k1) * 16 + j];
            g_DP[e] = pack2(d0, d1);
            g_AP[e] = pack2(aw1[(384 + k0) * 16 + j], aw1[(384 + k1) * 16 + j]);
        }
    } else if (blk == 9) {
        for (int idx = tid; idx < 2048; idx += 256) {
            int k = idx >> 4, j = idx & 15;
            g_S[idx] = aw1[k * 16 + j] + aw1[(256 + k) * 16 + j];
        }
    } else if (blk == 10) {
        for (int idx = tid; idx < 4096; idx += 256) {
            int d = idx >> 4;
            float g = bn_gamma[d] * rsqrtf(bn_var[d] + 1e-3f);
            g_w1g[idx] = w1[idx] * g;
        }
    } else {
        __shared__ float red[256];
        int j = tid & 15, ch = tid >> 4;
        float p = 0.0f;
        #pragma unroll
        for (int r = 0; r < 16; r++) {
            int d = ch * 16 + r;
            float g = bn_gamma[d] * rsqrtf(bn_var[d] + 1e-3f);
            float off = bn_beta[d] - bn_mean[d] * g;
            p = fmaf(off, w1[d * 16 + j], p);
        }
        red[ch * 16 + j] = p;
        __syncthreads();
        if (tid < 16) {
            float a = b1[tid];
            #pragma unroll
            for (int c2 = 0; c2 < 16; c2++) a += red[c2 * 16 + tid];
            g_b1p[tid] = a;
        }
    }
}

// ---- dynamic smem layout ----
struct DSmem {
    unsigned long long hp[64 * HPS];   // pair-transposed h chunk: hp[kp][t]
    unsigned long long wp[1024];       // W_eff paired [kp*16+j]
    unsigned long long r8[256];        // u64 reduction scratch
    float q[128];
    float cb[16];
    float sc[200];                     // exp(score) for all T
    float redf[256];
    float aw2s[128];
    float ab2s[8];
    float aw3s[8];
    float misc[8];                     // [2]=invZ [3]=out scalar
    float s1[16];
    float s2[8];
    int   hid[200];
};

__global__ void __launch_bounds__(256, 3) din_main(
    const int* __restrict__ iidx, const int* __restrict__ hist_i,
    const int* __restrict__ sl, const int* __restrict__ category_list,
    const float* __restrict__ item_emb, const float* __restrict__ cat_emb,
    const float* __restrict__ ab1,
    const float* __restrict__ aw2, const float* __restrict__ ab2,
    const float* __restrict__ aw3, const float* __restrict__ ab3,
    const float* __restrict__ aw4, const float* __restrict__ ab4,
    const float* __restrict__ w2, const float* __restrict__ b2,
    const float* __restrict__ w3, const float* __restrict__ b3,
    float* __restrict__ out)
{
    extern __shared__ char smraw[];
    DSmem& s = *reinterpret_cast<DSmem*>(smraw);

    const int b    = blockIdx.x;
    const int tid  = threadIdx.x;
    const int warp = tid >> 5, lane = tid & 31;

    const int ib   = iidx[b];
    const int icat = category_list[ib];
    const int slb  = sl[b];

    // ---- phase 0 ----
    if (tid < 128) s.q[tid] = (tid < 64) ? item_emb[(size_t)ib * EE + tid]
                                         : cat_emb[(size_t)icat * EE + (tid - 64)];
    if (tid < 200) s.hid[tid] = hist_i[b * TT + tid];
    if (tid < 128) s.aw2s[tid] = aw2[tid];
    if (tid < 8) { s.ab2s[tid] = ab2[tid]; s.aw3s[tid] = aw3[tid]; }
    if (tid == 0) s.misc[0] = ab3[0];
    __syncthreads();

    // ---- phase 1: W_eff (f32x2) + cb ----
    #pragma unroll
    for (int e = tid; e < 1024; e += 256) {
        int kp = e >> 4;
        unsigned long long qp = *(const unsigned long long*)(s.q + 2 * kp);
        unsigned long long d  = g_DP[e];
        ffma2(d, qp, g_AP[e]);
        s.wp[e] = d;
    }
    {
        int j = tid & 15, ch = tid >> 4;   // 16 chunks x 8 k
        float p = 0.0f;
        #pragma unroll
        for (int r = 0; r < 8; r++) {
            int k = ch * 8 + r;
            p = fmaf(s.q[k], g_S[k * 16 + j], p);
        }
        s.redf[ch * 16 + j] = p;
    }
    __syncthreads();
    if (tid < 16) {
        float a = ab1[tid];
        #pragma unroll
        for (int ch = 0; ch < 16; ch++) a += s.redf[ch * 16 + tid];
        s.cb[tid] = a;
    }
    __syncthreads();

    // ---- chunked: stage -> scores -> streamed weighted sum ----
    unsigned long long acc2 = 0;           // per-thread: kp=tid&63, quarter tid>>6
    const int kpw = tid & 63, q4 = tid >> 6;

    #pragma unroll 1
    for (int c = 0; c < 2; c++) {
        const int tbase = c * TC;

        // stage: warp-cooperative coalesced row loads (2 wavefronts/row)
        for (int r = warp; r < 2 * TC; r += 8) {
            int tl = r >> 1, table = r & 1;
            int hd = s.hid[tbase + tl];
            const float* src = table ? cat_emb : item_emb;
            unsigned long long v =
                *(const unsigned long long*)(src + (size_t)hd * EE + 2 * lane);
            s.hp[(table * 32 + lane) * HPS + tl] = v;
        }
        __syncthreads();

        // scores (thread-per-t)
        if (tid < TC) {
            int tg = tbase + tid;
            float e = 0.0f;
            if (tg < slb) {
                unsigned long long a2[16];
                #pragma unroll
                for (int j = 0; j < 16; j++) a2[j] = pack2(s.cb[j], 0.0f);
                #pragma unroll 4
                for (int kp = 0; kp < 64; kp++) {
                    unsigned long long hv = s.hp[kp * HPS + tid];
                    const ulonglong2* wv = (const ulonglong2*)(s.wp + kp * 16);
                    #pragma unroll
                    for (int jj = 0; jj < 8; jj++) {
                        ulonglong2 w = wv[jj];
                        ffma2(a2[2 * jj],     hv, w.x);
                        ffma2(a2[2 * jj + 1], hv, w.y);
                    }
                }
                float x1[16];
                #pragma unroll
                for (int j = 0; j < 16; j++) {
                    float lo, hi; unpack2(a2[j], lo, hi);
                    x1[j] = sigmoid_sw(lo + hi);
                }
                float y[8];
                #pragma unroll
                for (int o = 0; o < 8; o++) y[o] = s.ab2s[o];
                #pragma unroll
                for (int j = 0; j < 16; j++) {
                    float xv = x1[j];
                    #pragma unroll
                    for (int o = 0; o < 8; o++) y[o] = fmaf(xv, s.aw2s[j * 8 + o], y[o]);
                }
                float sv = s.misc[0];
                #pragma unroll
                for (int o = 0; o < 8; o++) sv = fmaf(sigmoid_sw(y[o]), s.aw3s[o], sv);
                // scores are sigmoid-bounded (|s|<~1) -> exp without max-shift is safe
                e = __expf(sv * 0.08838834764831844f);
            }
            s.sc[tg] = e;
        }
        __syncthreads();

        // streamed weighted sum while chunk is in smem
        {
            int t0 = q4 * 25;
            #pragma unroll 5
            for (int tl = t0; tl < t0 + 25; tl++) {
                float ev = s.sc[tbase + tl];
                unsigned long long ep = pack2(ev, ev);
                ffma2(acc2, ep, s.hp[kpw * HPS + tl]);
            }
        }
        __syncthreads();   // protect hp before next chunk's staging
    }
    s.r8[tid] = acc2;
    __syncthreads();

    // Z = sum of exp-scores
    if (tid < 32) {
        float z = 0.0f;
        for (int t = tid; t < TT; t += 32) z += s.sc[t];
        #pragma unroll
        for (int o = 16; o; o >>= 1) z += __shfl_xor_sync(0xffffffffu, z, o);
        if (tid == 0) s.misc[2] = 1.0f / z;
    }
    __syncthreads();

    // h1[k] (normalized) -> redf[0..128)
    if (tid < 64) {
        float iz = s.misc[2];
        float lo0, hi0, lo1, hi1, lo2, hi2, lo3, hi3;
        unpack2(s.r8[tid],        lo0, hi0);
        unpack2(s.r8[64  + tid],  lo1, hi1);
        unpack2(s.r8[128 + tid],  lo2, hi2);
        unpack2(s.r8[192 + tid],  lo3, hi3);
        s.redf[2 * tid]     = (lo0 + lo1 + lo2 + lo3) * iz;
        s.redf[2 * tid + 1] = (hi0 + hi1 + hi2 + hi3) * iz;
    }
    __syncthreads();

    // h2 = h1 @ aw4 (split-k by 2), partials into r8 (as floats)
    {
        int col = tid & 127, hf = tid >> 7;
        float a = 0.0f;
        int k0 = hf * 64;
        #pragma unroll 4
        for (int k = k0; k < k0 + 64; k++)
            a = fmaf(s.redf[k], aw4[k * 128 + col], a);
        ((float*)s.r8)[hf * 128 + col] = a;
    }
    __syncthreads();

    // head MLP with BN folded: s1[j] = b1p[j] + sum_d v_d * w1g[d][j]
    {
        int j = tid & 15, ch = tid >> 4;   // 16 chunks x 16 d
        const float* r8f = (const float*)s.r8;
        float p = 0.0f;
        #pragma unroll
        for (int r = 0; r < 16; r++) {
            int d = ch * 16 + r;
            float v = (d < 128) ? (r8f[d] + r8f[128 + d] + ab4[d]) : s.q[d - 128];
            p = fmaf(v, g_w1g[d * 16 + j], p);
        }
        s.redf[ch * 16 + j] = p;
    }
    __syncthreads();
    if (tid < 16) {
        float a = g_b1p[tid];
        #pragma unroll
        for (int ch = 0; ch < 16; ch++) a += s.redf[ch * 16 + tid];
        s.s1[tid] = a;
    }
    __syncthreads();
    if (tid < 8) {
        float a = b2[tid];
        #pragma unroll
        for (int j = 0; j < 16; j++) a = fmaf(s.s1[j], w2[j * 8 + tid], a);
        s.s2[tid] = a;
    }
    __syncthreads();
    if (tid == 0) {
        float a = b3[0];
        #pragma unroll
        for (int o = 0; o < 8; o++) a = fmaf(s.s2[o], w3[o], a);
        s.misc[3] = a;
    }
    __syncthreads();

    // fused output row: out[b][c] = scalar_b + item_b[i[c]]
    float s3 = s.misc[3];
    const float4* g4 = (const float4*)g_ibg;
    float4* o4 = (float4*)(out + (size_t)b * BB);
    #pragma unroll
    for (int c4 = tid; c4 < BB / 4; c4 += 256) {
        float4 v = g4[c4];
        v.x += s3; v.y += s3; v.z += s3; v.w += s3;
        o4[c4] = v;
    }
}

extern "C" void kernel_launch(void* const* d_in, const int* in_sizes, int n_in,
                              void* d_out, int out_size) {
    const int*   i_arr   = (const int*)d_in[1];
    const int*   hist_i  = (const int*)d_in[2];
    const int*   sl      = (const int*)d_in[3];
    const int*   catlist = (const int*)d_in[4];
    const float* item_emb = (const float*)d_in[5];
    const float* cat_emb  = (const float*)d_in[6];
    const float* item_b   = (const float*)d_in[7];
    const float* aw1 = (const float*)d_in[8];
    const float* ab1 = (const float*)d_in[9];
    const float* aw2 = (const float*)d_in[10];
    const float* ab2 = (const float*)d_in[11];
    const float* aw3 = (const float*)d_in[12];
    const float* ab3 = (const float*)d_in[13];
    const float* aw4 = (const float*)d_in[14];
    const float* ab4 = (const float*)d_in[15];
    const float* bn_gamma = (const float*)d_in[16];
    const float* bn_beta  = (const float*)d_in[17];
    const float* bn_mean  = (const float*)d_in[18];
    const float* bn_var   = (const float*)d_in[19];
    const float* w1 = (const float*)d_in[20];
    const float* b1 = (const float*)d_in[21];
    const float* w2 = (const float*)d_in[22];
    const float* b2 = (const float*)d_in[23];
    const float* w3 = (const float*)d_in[24];
    const float* b3 = (const float*)d_in[25];
    float* out = (float*)d_out;

    static int smem_set = 0;
    if (!smem_set) {
        cudaFuncSetAttribute(din_main, cudaFuncAttributeMaxDynamicSharedMemorySize,
                             (int)sizeof(DSmem));
        smem_set = 1;
    }

    k0_kernel<<<12, 256>>>(i_arr, item_b, aw1, bn_gamma, bn_beta, bn_mean, bn_var,
                           w1, b1);
    din_main<<<BB, 256, sizeof(DSmem)>>>(
        i_arr, hist_i, sl, catlist, item_emb, cat_emb,
        ab1, aw2, ab2, aw3, ab3, aw4, ab4,
        w2, b2, w3, b3, out);
}

// round 4
// speedup vs baseline: 2.1082x; 1.1327x over previous
#include <cuda_runtime.h>
#include <cuda_bf16.h>
#include <math.h>

#define BB 2048
#define TT 200
#define EE 64
#define TC 100

// ---- persistent device scratch (b-invariant precompute) ----
__device__ float              g_ibg[BB];      // item_b[i[c]]
__device__ unsigned long long g_DP[1024];     // (A2-A3) pairs, [j*64+kp]
__device__ unsigned long long g_AP[1024];     // A4 pairs,      [j*64+kp]
__device__ float              g_S[2048];      // A1+A3          [k*16+j]
__device__ float              g_w1g[4096];    // BN-folded w1   [d*16+j]
__device__ float              g_b1p[16];      // BN-folded b1

__device__ __forceinline__ void ffma2(unsigned long long& d,
                                      unsigned long long a,
                                      unsigned long long b) {
    asm("fma.rn.f32x2 %0, %1, %2, %0;" : "+l"(d) : "l"(a), "l"(b));
}
__device__ __forceinline__ unsigned long long pack2(float lo, float hi) {
    unsigned long long r;
    asm("mov.b64 %0, {%1, %2};" : "=l"(r) : "f"(lo), "f"(hi));
    return r;
}
__device__ __forceinline__ void unpack2(unsigned long long v, float& lo, float& hi) {
    asm("mov.b64 {%0, %1}, %2;" : "=f"(lo), "=f"(hi) : "l"(v));
}

// MUFU sigmoid: ex2.approx + rcp.approx (FMA pipe is the loaded one).
__device__ __forceinline__ float sigmoid_fast(float x) {
    float e;
    asm("ex2.approx.f32 %0, %1;" : "=f"(e) : "f"(x * -1.4426950408889634f));
    float d = 1.0f + e, r;
    asm("rcp.approx.f32 %0, %1;" : "=f"(r) : "f"(d));
    return r;
}

__device__ __forceinline__ void mma_tf32(float& d0, float& d1, float& d2, float& d3,
                                         unsigned a0, unsigned a1, unsigned a2, unsigned a3,
                                         unsigned b0, unsigned b1) {
    asm volatile(
        "mma.sync.aligned.m16n8k8.row.col.f32.tf32.tf32.f32 "
        "{%0,%1,%2,%3}, {%4,%5,%6,%7}, {%8,%9}, {%0,%1,%2,%3};"
        : "+f"(d0), "+f"(d1), "+f"(d2), "+f"(d3)
        : "r"(a0), "r"(a1), "r"(a2), "r"(a3), "r"(b0), "r"(b1));
}

// ---- K0: b-invariant precompute ----
__global__ void k0_kernel(const int* __restrict__ iidx, const float* __restrict__ item_b,
                          const float* __restrict__ aw1,
                          const float* __restrict__ bn_gamma, const float* __restrict__ bn_beta,
                          const float* __restrict__ bn_mean, const float* __restrict__ bn_var,
                          const float* __restrict__ w1, const float* __restrict__ b1) {
    int blk = blockIdx.x, tid = threadIdx.x;
    if (blk < 8) {
        int c = blk * 256 + tid;
        g_ibg[c] = item_b[iidx[c]];
    } else if (blk == 8) {
        for (int e = tid; e < 1024; e += 256) {
            int j = e >> 6, kp = e & 63;
            int k0 = 2 * kp, k1 = k0 + 1;
            float d0 = aw1[(128 + k0) * 16 + j] - aw1[(256 + k0) * 16 + j];
            float d1 = aw1[(128 + k1) * 16 + j] - aw1[(256 + k1) * 16 + j];
            g_DP[e] = pack2(d0, d1);
            g_AP[e] = pack2(aw1[(384 + k0) * 16 + j], aw1[(384 + k1) * 16 + j]);
        }
    } else if (blk == 9) {
        for (int idx = tid; idx < 2048; idx += 256) {
            int k = idx >> 4, j = idx & 15;
            g_S[idx] = aw1[k * 16 + j] + aw1[(256 + k) * 16 + j];
        }
    } else if (blk == 10) {
        for (int idx = tid; idx < 4096; idx += 256) {
            int d = idx >> 4;
            float g = bn_gamma[d] * rsqrtf(bn_var[d] + 1e-3f);
            g_w1g[idx] = w1[idx] * g;
        }
    } else {
        __shared__ float red[256];
        int j = tid & 15, ch = tid >> 4;
        float p = 0.0f;
        #pragma unroll
        for (int r = 0; r < 16; r++) {
            int d = ch * 16 + r;
            float g = bn_gamma[d] * rsqrtf(bn_var[d] + 1e-3f);
            float off = bn_beta[d] - bn_mean[d] * g;
            p = fmaf(off, w1[d * 16 + j], p);
        }
        red[ch * 16 + j] = p;
        __syncthreads();
        if (tid < 16) {
            float a = b1[tid];
            #pragma unroll
            for (int c2 = 0; c2 < 16; c2++) a += red[c2 * 16 + tid];
            g_b1p[tid] = a;
        }
    }
}

// smem: h FIRST, Wt immediately after (mma A-tile pad rows 100..111 read into Wt,
// masked later — never stored).
struct Smem {
    float h[TC * 128];      // staged h chunk, [t][k], col XOR-swizzled by (t&7)<<2
    float wt[16 * 128];     // W_eff [j][k], col XOR-swizzled by (j&7)<<2
    float accs[TC * 18];    // mma D: [t][j], stride 18
    unsigned long long r8[256];
    float q[128];
    float cb[16];
    float sc[200];
    float redf[256];
    float aw2s[128];
    float ab2s[8], aw3s[8], misc[8];
    float s1[16], s2[8];
    int   hid[200];
};

__global__ void __launch_bounds__(256, 3) din_main(
    const int* __restrict__ iidx, const int* __restrict__ hist_i,
    const int* __restrict__ sl, const int* __restrict__ category_list,
    const float* __restrict__ item_emb, const float* __restrict__ cat_emb,
    const float* __restrict__ ab1,
    const float* __restrict__ aw2, const float* __restrict__ ab2,
    const float* __restrict__ aw3, const float* __restrict__ ab3,
    const float* __restrict__ aw4, const float* __restrict__ ab4,
    const float* __restrict__ w2, const float* __restrict__ b2,
    const float* __restrict__ w3, const float* __restrict__ b3,
    float* __restrict__ out)
{
    extern __shared__ char smraw[];
    Smem& s = *reinterpret_cast<Smem*>(smraw);

    const int b    = blockIdx.x;
    const int tid  = threadIdx.x;
    const int warp = tid >> 5, lane = tid & 31;

    const int ib   = iidx[b];
    const int icat = category_list[ib];
    const int slb  = sl[b];

    // ---- phase 0 ----
    if (tid < 128) s.q[tid] = (tid < 64) ? item_emb[(size_t)ib * EE + tid]
                                         : cat_emb[(size_t)icat * EE + (tid - 64)];
    if (tid < 200) s.hid[tid] = hist_i[b * TT + tid];
    if (tid < 128) s.aw2s[tid] = aw2[tid];
    if (tid < 8) { s.ab2s[tid] = ab2[tid]; s.aw3s[tid] = aw3[tid]; }
    if (tid == 0) s.misc[0] = ab3[0];
    __syncthreads();

    // ---- phase 1: W_eff -> Wt[j][k] (swizzled) + cb ----
    #pragma unroll
    for (int e = tid; e < 1024; e += 256) {
        int j = e >> 6, kp = e & 63;
        unsigned long long qp = *(const unsigned long long*)(s.q + 2 * kp);
        unsigned long long d  = g_DP[e];
        ffma2(d, qp, g_AP[e]);
        int col = (2 * kp) ^ ((j & 7) << 2);
        *(unsigned long long*)(s.wt + j * 128 + col) = d;
    }
    {
        int j = tid & 15, ch = tid >> 4;
        float p = 0.0f;
        #pragma unroll
        for (int r = 0; r < 8; r++) {
            int k = ch * 8 + r;
            p = fmaf(s.q[k], g_S[k * 16 + j], p);
        }
        s.redf[ch * 16 + j] = p;
    }
    __syncthreads();
    if (tid < 16) {
        float a = ab1[tid];
        #pragma unroll
        for (int ch = 0; ch < 16; ch++) a += s.redf[ch * 16 + tid];
        s.cb[tid] = a;
    }
    __syncthreads();

    unsigned long long acc2 = 0;                 // weighted-sum accumulator
    const int kpw = tid & 63, q4 = tid >> 6;

    #pragma unroll 1
    for (int c = 0; c < 2; c++) {
        const int tbase = c * TC;

        // stage h[t][k] (XOR swizzle), coalesced warp-per-row
        for (int r = warp; r < 2 * TC; r += 8) {
            int tl = r >> 1, table = r & 1;
            int hd = s.hid[tbase + tl];
            const float* src = table ? cat_emb : item_emb;
            unsigned long long v =
                *(const unsigned long long*)(src + (size_t)hd * EE + 2 * lane);
            int col = (table * 64 + 2 * lane) ^ ((tl & 7) << 2);
            *(unsigned long long*)(s.h + tl * 128 + col) = v;
        }
        __syncthreads();

        // mma: acc[t][j] = sum_k h[t][k] * W[k][j]  (tf32, warps 0..6)
        if (warp < 7) {
            int g = lane >> 2, qd = lane & 3;
            int t0 = warp * 16 + g;
            int xsw = g << 2;
            const float* hA0 = s.h + t0 * 128;
            const float* hA1 = hA0 + 8 * 128;
            const float* bB  = s.wt + g * 128;
            float d00 = 0.f, d01 = 0.f, d02 = 0.f, d03 = 0.f;
            float d10 = 0.f, d11 = 0.f, d12 = 0.f, d13 = 0.f;
            #pragma unroll
            for (int ks = 0; ks < 16; ks++) {
                int c1 = (8 * ks + qd) ^ xsw;
                int c2 = c1 ^ 4;
                unsigned a0 = __float_as_uint(hA0[c1]);
                unsigned a1 = __float_as_uint(hA1[c1]);
                unsigned a2 = __float_as_uint(hA0[c2]);
                unsigned a3 = __float_as_uint(hA1[c2]);
                unsigned b0 = __float_as_uint(bB[c1]);
                unsigned b1 = __float_as_uint(bB[c2]);
                unsigned b2 = __float_as_uint(bB[8 * 128 + c1]);
                unsigned b3 = __float_as_uint(bB[8 * 128 + c2]);
                mma_tf32(d00, d01, d02, d03, a0, a1, a2, a3, b0, b1);
                mma_tf32(d10, d11, d12, d13, a0, a1, a2, a3, b2, b3);
            }
            float* ar0 = s.accs + t0 * 18 + 2 * qd;
            if (t0 < TC) {
                ar0[0] = d00; ar0[1] = d01; ar0[8] = d10; ar0[9] = d11;
            }
            if (t0 + 8 < TC) {
                float* ar1 = ar0 + 8 * 18;
                ar1[0] = d02; ar1[1] = d03; ar1[8] = d12; ar1[9] = d13;
            }
        }
        __syncthreads();

        // per-t sigmoid MLP -> exp(score)
        if (tid < TC) {
            int tg = tbase + tid;
            float e = 0.0f;
            if (tg < slb) {
                const float* arow = s.accs + tid * 18;
                float x1[16];
                #pragma unroll
                for (int j = 0; j < 16; j++)
                    x1[j] = sigmoid_fast(arow[j] + s.cb[j]);
                float y[8];
                #pragma unroll
                for (int o = 0; o < 8; o++) y[o] = s.ab2s[o];
                #pragma unroll
                for (int j = 0; j < 16; j++) {
                    float xv = x1[j];
                    #pragma unroll
                    for (int o = 0; o < 8; o++) y[o] = fmaf(xv, s.aw2s[j * 8 + o], y[o]);
                }
                float sv = s.misc[0];
                #pragma unroll
                for (int o = 0; o < 8; o++) sv = fmaf(sigmoid_fast(y[o]), s.aw3s[o], sv);
                e = __expf(sv * 0.08838834764831844f);  // scores bounded -> no max-shift
            }
            s.sc[tg] = e;
        }
        __syncthreads();

        // streamed weighted sum while chunk is in smem
        {
            int t0q = q4 * 25;
            #pragma unroll 5
            for (int tl = t0q; tl < t0q + 25; tl++) {
                float ev = s.sc[tbase + tl];
                int col = (2 * kpw) ^ ((tl & 7) << 2);
                unsigned long long hv = *(const unsigned long long*)(s.h + tl * 128 + col);
                ffma2(acc2, pack2(ev, ev), hv);
            }
        }
        __syncthreads();
    }
    s.r8[tid] = acc2;
    __syncthreads();

    // Z = sum exp
    if (tid < 32) {
        float z = 0.0f;
        for (int t = tid; t < TT; t += 32) z += s.sc[t];
        #pragma unroll
        for (int o = 16; o; o >>= 1) z += __shfl_xor_sync(0xffffffffu, z, o);
        if (tid == 0) s.misc[2] = 1.0f / z;
    }
    __syncthreads();

    // h1
    if (tid < 64) {
        float iz = s.misc[2];
        float lo0, hi0, lo1, hi1, lo2, hi2, lo3, hi3;
        unpack2(s.r8[tid],       lo0, hi0);
        unpack2(s.r8[64 + tid],  lo1, hi1);
        unpack2(s.r8[128 + tid], lo2, hi2);
        unpack2(s.r8[192 + tid], lo3, hi3);
        s.redf[2 * tid]     = (lo0 + lo1 + lo2 + lo3) * iz;
        s.redf[2 * tid + 1] = (hi0 + hi1 + hi2 + hi3) * iz;
    }
    __syncthreads();

    // h2 = h1 @ aw4 (split-k by 2)
    {
        int col = tid & 127, hf = tid >> 7;
        float a = 0.0f;
        int k0 = hf * 64;
        #pragma unroll 4
        for (int k = k0; k < k0 + 64; k++)
            a = fmaf(s.redf[k], aw4[k * 128 + col], a);
        ((float*)s.r8)[hf * 128 + col] = a;
    }
    __syncthreads();

    // head MLP, BN folded
    {
        int j = tid & 15, ch = tid >> 4;
        const float* r8f = (const float*)s.r8;
        float p = 0.0f;
        #pragma unroll
        for (int r = 0; r < 16; r++) {
            int d = ch * 16 + r;
            float v = (d < 128) ? (r8f[d] + r8f[128 + d] + ab4[d]) : s.q[d - 128];
            p = fmaf(v, g_w1g[d * 16 + j], p);
        }
        s.redf[ch * 16 + j] = p;
    }
    __syncthreads();
    if (tid < 16) {
        float a = g_b1p[tid];
        #pragma unroll
        for (int ch = 0; ch < 16; ch++) a += s.redf[ch * 16 + tid];
        s.s1[tid] = a;
    }
    __syncthreads();
    if (tid < 8) {
        float a = b2[tid];
        #pragma unroll
        for (int j = 0; j < 16; j++) a = fmaf(s.s1[j], w2[j * 8 + tid], a);
        s.s2[tid] = a;
    }
    __syncthreads();
    if (tid == 0) {
        float a = b3[0];
        #pragma unroll
        for (int o = 0; o < 8; o++) a = fmaf(s.s2[o], w3[o], a);
        s.misc[3] = a;
    }
    __syncthreads();

    // fused output row
    float s3 = s.misc[3];
    const float4* g4 = (const float4*)g_ibg;
    float4* o4 = (float4*)(out + (size_t)b * BB);
    #pragma unroll
    for (int c4 = tid; c4 < BB / 4; c4 += 256) {
        float4 v = g4[c4];
        v.x += s3; v.y += s3; v.z += s3; v.w += s3;
        o4[c4] = v;
    }
}

extern "C" void kernel_launch(void* const* d_in, const int* in_sizes, int n_in,
                              void* d_out, int out_size) {
    const int*   i_arr   = (const int*)d_in[1];
    const int*   hist_i  = (const int*)d_in[2];
    const int*   sl      = (const int*)d_in[3];
    const int*   catlist = (const int*)d_in[4];
    const float* item_emb = (const float*)d_in[5];
    const float* cat_emb  = (const float*)d_in[6];
    const float* item_b   = (const float*)d_in[7];
    const float* aw1 = (const float*)d_in[8];
    const float* ab1 = (const float*)d_in[9];
    const float* aw2 = (const float*)d_in[10];
    const float* ab2 = (const float*)d_in[11];
    const float* aw3 = (const float*)d_in[12];
    const float* ab3 = (const float*)d_in[13];
    const float* aw4 = (const float*)d_in[14];
    const float* ab4 = (const float*)d_in[15];
    const float* bn_gamma = (const float*)d_in[16];
    const float* bn_beta  = (const float*)d_in[17];
    const float* bn_mean  = (const float*)d_in[18];
    const float* bn_var   = (const float*)d_in[19];
    const float* w1 = (const float*)d_in[20];
    const float* b1 = (const float*)d_in[21];
    const float* w2 = (const float*)d_in[22];
    const float* b2 = (const float*)d_in[23];
    const float* w3 = (const float*)d_in[24];
    const float* b3 = (const float*)d_in[25];
    float* out = (float*)d_out;

    static int smem_set = 0;
    if (!smem_set) {
        cudaFuncSetAttribute(din_main, cudaFuncAttributeMaxDynamicSharedMemorySize,
                             (int)sizeof(Smem));
        smem_set = 1;
    }

    k0_kernel<<<12, 256>>>(i_arr, item_b, aw1, bn_gamma, bn_beta, bn_mean, bn_var,
                           w1, b1);
    din_main<<<BB, 256, sizeof(Smem)>>>(
        i_arr, hist_i, sl, catlist, item_emb, cat_emb,
        ab1, aw2, ab2, aw3, ab3, aw4, ab4,
        w2, b2, w3, b3, out);
}

// round 5
// speedup vs baseline: 3.1208x; 1.4804x over previous
#include <cuda_runtime.h>
#include <cuda_bf16.h>
#include <math.h>

#define BB 2048
#define TT 200
#define EE 64
#define TC 50

// ---- persistent device scratch (b-invariant precompute) ----
__device__ float              g_ibg[BB];      // item_b[i[c]]
__device__ unsigned long long g_DP[1024];     // (A2-A3) pairs, [j*64+kp]
__device__ unsigned long long g_AP[1024];     // A4 pairs,      [j*64+kp]
__device__ float              g_S[2048];      // A1+A3          [k*16+j]
__device__ float              g_w1g[4096];    // BN-folded w1   [d*16+j]
__device__ float              g_b1p[16];      // BN-folded b1

__device__ __forceinline__ void ffma2(unsigned long long& d,
                                      unsigned long long a,
                                      unsigned long long b) {
    asm("fma.rn.f32x2 %0, %1, %2, %0;" : "+l"(d) : "l"(a), "l"(b));
}
__device__ __forceinline__ unsigned long long pack2(float lo, float hi) {
    unsigned long long r;
    asm("mov.b64 %0, {%1, %2};" : "=l"(r) : "f"(lo), "f"(hi));
    return r;
}
__device__ __forceinline__ void unpack2(unsigned long long v, float& lo, float& hi) {
    asm("mov.b64 {%0, %1}, %2;" : "=f"(lo), "=f"(hi) : "l"(v));
}

__device__ __forceinline__ float sigmoid_fast(float x) {
    float e;
    asm("ex2.approx.f32 %0, %1;" : "=f"(e) : "f"(x * -1.4426950408889634f));
    float d = 1.0f + e, r;
    asm("rcp.approx.f32 %0, %1;" : "=f"(r) : "f"(d));
    return r;
}

__device__ __forceinline__ void mma_tf32(float& d0, float& d1, float& d2, float& d3,
                                         unsigned a0, unsigned a1, unsigned a2, unsigned a3,
                                         unsigned b0, unsigned b1) {
    asm volatile(
        "mma.sync.aligned.m16n8k8.row.col.f32.tf32.tf32.f32 "
        "{%0,%1,%2,%3}, {%4,%5,%6,%7}, {%8,%9}, {%0,%1,%2,%3};"
        : "+f"(d0), "+f"(d1), "+f"(d2), "+f"(d3)
        : "r"(a0), "r"(a1), "r"(a2), "r"(a3), "r"(b0), "r"(b1));
}

// ---- K0: b-invariant precompute ----
__global__ void k0_kernel(const int* __restrict__ iidx, const float* __restrict__ item_b,
                          const float* __restrict__ aw1,
                          const float* __restrict__ bn_gamma, const float* __restrict__ bn_beta,
                          const float* __restrict__ bn_mean, const float* __restrict__ bn_var,
                          const float* __restrict__ w1, const float* __restrict__ b1) {
    int blk = blockIdx.x, tid = threadIdx.x;
    if (blk < 8) {
        int c = blk * 256 + tid;
        g_ibg[c] = item_b[iidx[c]];
    } else if (blk == 8) {
        for (int e = tid; e < 1024; e += 256) {
            int j = e >> 6, kp = e & 63;
            int k0 = 2 * kp, k1 = k0 + 1;
            float d0 = aw1[(128 + k0) * 16 + j] - aw1[(256 + k0) * 16 + j];
            float d1 = aw1[(128 + k1) * 16 + j] - aw1[(256 + k1) * 16 + j];
            g_DP[e] = pack2(d0, d1);
            g_AP[e] = pack2(aw1[(384 + k0) * 16 + j], aw1[(384 + k1) * 16 + j]);
        }
    } else if (blk == 9) {
        for (int idx = tid; idx < 2048; idx += 256) {
            int k = idx >> 4, j = idx & 15;
            g_S[idx] = aw1[k * 16 + j] + aw1[(256 + k) * 16 + j];
        }
    } else if (blk == 10) {
        for (int idx = tid; idx < 4096; idx += 256) {
            int d = idx >> 4;
            float g = bn_gamma[d] * rsqrtf(bn_var[d] + 1e-3f);
            g_w1g[idx] = w1[idx] * g;
        }
    } else {
        __shared__ float red[256];
        int j = tid & 15, ch = tid >> 4;
        float p = 0.0f;
        #pragma unroll
        for (int r = 0; r < 16; r++) {
            int d = ch * 16 + r;
            float g = bn_gamma[d] * rsqrtf(bn_var[d] + 1e-3f);
            float off = bn_beta[d] - bn_mean[d] * g;
            p = fmaf(off, w1[d * 16 + j], p);
        }
        red[ch * 16 + j] = p;
        __syncthreads();
        if (tid < 16) {
            float a = b1[tid];
            #pragma unroll
            for (int c2 = 0; c2 < 16; c2++) a += red[c2 * 16 + tid];
            g_b1p[tid] = a;
        }
    }
}

// h FIRST, wt immediately after: MMA A-tile rows 50..63 overflow into wt
// (read-only, finite, masked via e=0 — never stored).
struct Smem {
    float h[TC * 128];      // staged h chunk [t][k], col ^= (t&7)<<2
    float wt[16 * 128];     // W_eff [j][k],  col ^= (j&7)<<2
    unsigned long long r8[256];
    float q[128];
    float cb[16];
    float sc[200];          // exp(score), pre-zeroed
    float redf[256];
    float aw2s[128];
    float ab2s[8], aw3s[8], misc[8];
    float s1[16], s2[8];
    int   hid[200];
};

__global__ void __launch_bounds__(256, 4) din_main(
    const int* __restrict__ iidx, const int* __restrict__ hist_i,
    const int* __restrict__ sl, const int* __restrict__ category_list,
    const float* __restrict__ item_emb, const float* __restrict__ cat_emb,
    const float* __restrict__ ab1,
    const float* __restrict__ aw2, const float* __restrict__ ab2,
    const float* __restrict__ aw3, const float* __restrict__ ab3,
    const float* __restrict__ aw4, const float* __restrict__ ab4,
    const float* __restrict__ w2, const float* __restrict__ b2,
    const float* __restrict__ w3, const float* __restrict__ b3,
    float* __restrict__ out)
{
    extern __shared__ char smraw[];
    Smem& s = *reinterpret_cast<Smem*>(smraw);

    const int b    = blockIdx.x;
    const int tid  = threadIdx.x;
    const int warp = tid >> 5, lane = tid & 31;

    const int ib   = iidx[b];
    const int icat = category_list[ib];
    const int slb  = sl[b];

    // ---- phase 0 ----
    if (tid < 128) s.q[tid] = (tid < 64) ? item_emb[(size_t)ib * EE + tid]
                                         : cat_emb[(size_t)icat * EE + (tid - 64)];
    if (tid < 200) { s.hid[tid] = hist_i[b * TT + tid]; s.sc[tid] = 0.0f; }
    if (tid < 128) s.aw2s[tid] = aw2[tid];
    if (tid < 8) { s.ab2s[tid] = ab2[tid]; s.aw3s[tid] = aw3[tid]; }
    if (tid == 0) s.misc[0] = ab3[0];
    __syncthreads();

    // ---- phase 1: W_eff -> wt[j][k] (swizzled) + cb ----
    #pragma unroll
    for (int e = tid; e < 1024; e += 256) {
        int j = e >> 6, kp = e & 63;
        unsigned long long qp = *(const unsigned long long*)(s.q + 2 * kp);
        unsigned long long d  = g_DP[e];
        ffma2(d, qp, g_AP[e]);
        int col = (2 * kp) ^ ((j & 7) << 2);
        *(unsigned long long*)(s.wt + j * 128 + col) = d;
    }
    {
        int j = tid & 15, ch = tid >> 4;
        float p = 0.0f;
        #pragma unroll
        for (int r = 0; r < 8; r++) {
            int k = ch * 8 + r;
            p = fmaf(s.q[k], g_S[k * 16 + j], p);
        }
        s.redf[ch * 16 + j] = p;
    }
    __syncthreads();
    if (tid < 16) {
        float a = ab1[tid];
        #pragma unroll
        for (int ch = 0; ch < 16; ch++) a += s.redf[ch * 16 + tid];
        s.cb[tid] = a;
    }
    __syncthreads();

    unsigned long long acc2 = 0;
    const int kpw = tid & 63, q4 = tid >> 6;

    #pragma unroll 1
    for (int c = 0; c < 4; c++) {
        const int tbase = c * TC;
        if (tbase >= slb) break;                 // slb block-uniform -> legal
        const int rem = min(TC, slb - tbase);

        // stage only active rows (coalesced warp-per-row)
        for (int r = warp; r < 2 * rem; r += 8) {
            int tl = r >> 1, table = r & 1;
            int hd = s.hid[tbase + tl];
            const float* src = table ? cat_emb : item_emb;
            unsigned long long v =
                *(const unsigned long long*)(src + (size_t)hd * EE + 2 * lane);
            int col = (table * 64 + 2 * lane) ^ ((tl & 7) << 2);
            *(unsigned long long*)(s.h + tl * 128 + col) = v;
        }
        __syncthreads();

        // mma + in-register sigmoid MLP (warps 0..3, rows warp*16..+15)
        if (warp < 4 && warp * 16 < rem) {
            int g = lane >> 2, qd = lane & 3;
            int trowA = warp * 16 + g, trowB = trowA + 8;
            int xsw = g << 2;
            const float* hA0 = s.h + trowA * 128;
            const float* hA1 = s.h + trowB * 128;
            const float* bB  = s.wt + g * 128;
            float d00 = 0.f, d01 = 0.f, d02 = 0.f, d03 = 0.f;
            float d10 = 0.f, d11 = 0.f, d12 = 0.f, d13 = 0.f;
            #pragma unroll
            for (int ks = 0; ks < 16; ks++) {
                int c1 = (8 * ks + qd) ^ xsw;
                int c2 = c1 ^ 4;
                unsigned a0 = __float_as_uint(hA0[c1]);
                unsigned a1 = __float_as_uint(hA1[c1]);
                unsigned a2 = __float_as_uint(hA0[c2]);
                unsigned a3 = __float_as_uint(hA1[c2]);
                unsigned b0 = __float_as_uint(bB[c1]);
                unsigned b1 = __float_as_uint(bB[c2]);
                unsigned b2v = __float_as_uint(bB[8 * 128 + c1]);
                unsigned b3v = __float_as_uint(bB[8 * 128 + c2]);
                mma_tf32(d00, d01, d02, d03, a0, a1, a2, a3, b0, b1);
                mma_tf32(d10, d11, d12, d13, a0, a1, a2, a3, b2v, b3v);
            }
            // lane owns j = {2qd, 2qd+1, 8+2qd, 9+2qd} for rows trowA, trowB
            int j0 = 2 * qd, j1 = j0 + 1, j2 = j0 + 8, j3 = j0 + 9;
            float cb0 = s.cb[j0], cb1 = s.cb[j1], cb2 = s.cb[j2], cb3 = s.cb[j3];
            float xA0 = sigmoid_fast(d00 + cb0), xA1 = sigmoid_fast(d01 + cb1);
            float xA2 = sigmoid_fast(d10 + cb2), xA3 = sigmoid_fast(d11 + cb3);
            float xB0 = sigmoid_fast(d02 + cb0), xB1 = sigmoid_fast(d03 + cb1);
            float xB2 = sigmoid_fast(d12 + cb2), xB3 = sigmoid_fast(d13 + cb3);
            float yA[8], yB[8];
            #pragma unroll
            for (int o = 0; o < 8; o++) {
                float w0 = s.aw2s[j0 * 8 + o], w1v = s.aw2s[j1 * 8 + o];
                float w2v = s.aw2s[j2 * 8 + o], w3v = s.aw2s[j3 * 8 + o];
                yA[o] = fmaf(xA0, w0, fmaf(xA1, w1v, fmaf(xA2, w2v, xA3 * w3v)));
                yB[o] = fmaf(xB0, w0, fmaf(xB1, w1v, fmaf(xB2, w2v, xB3 * w3v)));
            }
            #pragma unroll
            for (int o = 0; o < 8; o++) {
                yA[o] += __shfl_xor_sync(0xffffffffu, yA[o], 1);
                yA[o] += __shfl_xor_sync(0xffffffffu, yA[o], 2);
                yB[o] += __shfl_xor_sync(0xffffffffu, yB[o], 1);
                yB[o] += __shfl_xor_sync(0xffffffffu, yB[o], 2);
            }
            int oa = 2 * qd, ob = oa + 1;
            float a2a = s.ab2s[oa], a2b = s.ab2s[ob];
            float a3a = s.aw3s[oa], a3b = s.aw3s[ob];
            float pA = fmaf(sigmoid_fast(yA[oa] + a2a), a3a,
                            sigmoid_fast(yA[ob] + a2b) * a3b);
            float pB = fmaf(sigmoid_fast(yB[oa] + a2a), a3a,
                            sigmoid_fast(yB[ob] + a2b) * a3b);
            pA += __shfl_xor_sync(0xffffffffu, pA, 1);
            pA += __shfl_xor_sync(0xffffffffu, pA, 2);
            pB += __shfl_xor_sync(0xffffffffu, pB, 1);
            pB += __shfl_xor_sync(0xffffffffu, pB, 2);
            if (qd == 0) {
                float ab3v = s.misc[0];
                if (trowA < TC) {
                    int tg = tbase + trowA;
                    s.sc[tg] = (tg < slb)
                        ? __expf((pA + ab3v) * 0.08838834764831844f) : 0.0f;
                }
                if (trowB < TC) {
                    int tg = tbase + trowB;
                    s.sc[tg] = (tg < slb)
                        ? __expf((pB + ab3v) * 0.08838834764831844f) : 0.0f;
                }
            }
        }
        __syncthreads();

        // streamed weighted sum over active rows
        for (int tl = q4; tl < rem; tl += 4) {
            float ev = s.sc[tbase + tl];
            int col = (2 * kpw) ^ ((tl & 7) << 2);
            unsigned long long hv = *(const unsigned long long*)(s.h + tl * 128 + col);
            ffma2(acc2, pack2(ev, ev), hv);
        }
        __syncthreads();
    }
    s.r8[tid] = acc2;
    __syncthreads();

    // Z
    if (tid < 32) {
        float z = 0.0f;
        for (int t = tid; t < TT; t += 32) z += s.sc[t];
        #pragma unroll
        for (int o = 16; o; o >>= 1) z += __shfl_xor_sync(0xffffffffu, z, o);
        if (tid == 0) s.misc[2] = 1.0f / z;
    }
    __syncthreads();

    // h1
    if (tid < 64) {
        float iz = s.misc[2];
        float lo0, hi0, lo1, hi1, lo2, hi2, lo3, hi3;
        unpack2(s.r8[tid],       lo0, hi0);
        unpack2(s.r8[64 + tid],  lo1, hi1);
        unpack2(s.r8[128 + tid], lo2, hi2);
        unpack2(s.r8[192 + tid], lo3, hi3);
        s.redf[2 * tid]     = (lo0 + lo1 + lo2 + lo3) * iz;
        s.redf[2 * tid + 1] = (hi0 + hi1 + hi2 + hi3) * iz;
    }
    __syncthreads();

    // h2 = h1 @ aw4 (split-k by 2)
    {
        int col = tid & 127, hf = tid >> 7;
        float a = 0.0f;
        int k0 = hf * 64;
        #pragma unroll 4
        for (int k = k0; k < k0 + 64; k++)
            a = fmaf(s.redf[k], aw4[k * 128 + col], a);
        ((float*)s.r8)[hf * 128 + col] = a;
    }
    __syncthreads();

    // head MLP, BN folded
    {
        int j = tid & 15, ch = tid >> 4;
        const float* r8f = (const float*)s.r8;
        float p = 0.0f;
        #pragma unroll
        for (int r = 0; r < 16; r++) {
            int d = ch * 16 + r;
            float v = (d < 128) ? (r8f[d] + r8f[128 + d] + ab4[d]) : s.q[d - 128];
            p = fmaf(v, g_w1g[d * 16 + j], p);
        }
        s.redf[ch * 16 + j] = p;
    }
    __syncthreads();
    if (tid < 16) {
        float a = g_b1p[tid];
        #pragma unroll
        for (int ch = 0; ch < 16; ch++) a += s.redf[ch * 16 + tid];
        s.s1[tid] = a;
    }
    __syncthreads();
    if (tid < 8) {
        float a = b2[tid];
        #pragma unroll
        for (int j = 0; j < 16; j++) a = fmaf(s.s1[j], w2[j * 8 + tid], a);
        s.s2[tid] = a;
    }
    __syncthreads();
    if (tid == 0) {
        float a = b3[0];
        #pragma unroll
        for (int o = 0; o < 8; o++) a = fmaf(s.s2[o], w3[o], a);
        s.misc[3] = a;
    }
    __syncthreads();

    // fused output row
    float s3 = s.misc[3];
    const float4* g4 = (const float4*)g_ibg;
    float4* o4 = (float4*)(out + (size_t)b * BB);
    #pragma unroll
    for (int c4 = tid; c4 < BB / 4; c4 += 256) {
        float4 v = g4[c4];
        v.x += s3; v.y += s3; v.z += s3; v.w += s3;
        o4[c4] = v;
    }
}

extern "C" void kernel_launch(void* const* d_in, const int* in_sizes, int n_in,
                              void* d_out, int out_size) {
    const int*   i_arr   = (const int*)d_in[1];
    const int*   hist_i  = (const int*)d_in[2];
    const int*   sl      = (const int*)d_in[3];
    const int*   catlist = (const int*)d_in[4];
    const float* item_emb = (const float*)d_in[5];
    const float* cat_emb  = (const float*)d_in[6];
    const float* item_b   = (const float*)d_in[7];
    const float* aw1 = (const float*)d_in[8];
    const float* ab1 = (const float*)d_in[9];
    const float* aw2 = (const float*)d_in[10];
    const float* ab2 = (const float*)d_in[11];
    const float* aw3 = (const float*)d_in[12];
    const float* ab3 = (const float*)d_in[13];
    const float* aw4 = (const float*)d_in[14];
    const float* ab4 = (const float*)d_in[15];
    const float* bn_gamma = (const float*)d_in[16];
    const float* bn_beta  = (const float*)d_in[17];
    const float* bn_mean  = (const float*)d_in[18];
    const float* bn_var   = (const float*)d_in[19];
    const float* w1 = (const float*)d_in[20];
    const float* b1 = (const float*)d_in[21];
    const float* w2 = (const float*)d_in[22];
    const float* b2 = (const float*)d_in[23];
    const float* w3 = (const float*)d_in[24];
    const float* b3 = (const float*)d_in[25];
    float* out = (float*)d_out;

    static int smem_set = 0;
    if (!smem_set) {
        cudaFuncSetAttribute(din_main, cudaFuncAttributeMaxDynamicSharedMemorySize,
                             (int)sizeof(Smem));
        smem_set = 1;
    }

    k0_kernel<<<12, 256>>>(i_arr, item_b, aw1, bn_gamma, bn_beta, bn_mean, bn_var,
                           w1, b1);
    din_main<<<BB, 256, sizeof(Smem)>>>(
        i_arr, hist_i, sl, catlist, item_emb, cat_emb,
        ab1, aw2, ab2, aw3, ab3, aw4, ab4,
        w2, b2, w3, b3, out);
}

// round 6
// speedup vs baseline: 3.1303x; 1.0030x over previous
#include <cuda_runtime.h>
#include <cuda_bf16.h>
#include <math.h>

#define BB 2048
#define TT 200
#define EE 64
#define TC 50

// ---- persistent device scratch (b-invariant precompute) ----
__device__ float              g_ibg[BB];      // item_b[i[c]]
__device__ unsigned long long g_DP[1024];     // (A2-A3) pairs, [j*64+kp]
__device__ unsigned long long g_AP[1024];     // A4 pairs,      [j*64+kp]
__device__ float              g_S[2048];      // A1+A3          [k*16+j]
__device__ float              g_w1g[4096];    // BN-folded w1   [d*16+j]
__device__ float              g_b1p[16];      // BN-folded b1

__device__ __forceinline__ void ffma2(unsigned long long& d,
                                      unsigned long long a,
                                      unsigned long long b) {
    asm("fma.rn.f32x2 %0, %1, %2, %0;" : "+l"(d) : "l"(a), "l"(b));
}
__device__ __forceinline__ unsigned long long pack2(float lo, float hi) {
    unsigned long long r;
    asm("mov.b64 %0, {%1, %2};" : "=l"(r) : "f"(lo), "f"(hi));
    return r;
}
__device__ __forceinline__ void unpack2(unsigned long long v, float& lo, float& hi) {
    asm("mov.b64 {%0, %1}, %2;" : "=f"(lo), "=f"(hi) : "l"(v));
}

__device__ __forceinline__ float sigmoid_fast(float x) {
    float e;
    asm("ex2.approx.f32 %0, %1;" : "=f"(e) : "f"(x * -1.4426950408889634f));
    float d = 1.0f + e, r;
    asm("rcp.approx.f32 %0, %1;" : "=f"(r) : "f"(d));
    return r;
}

__device__ __forceinline__ void mma_tf32(float& d0, float& d1, float& d2, float& d3,
                                         unsigned a0, unsigned a1, unsigned a2, unsigned a3,
                                         unsigned b0, unsigned b1) {
    asm volatile(
        "mma.sync.aligned.m16n8k8.row.col.f32.tf32.tf32.f32 "
        "{%0,%1,%2,%3}, {%4,%5,%6,%7}, {%8,%9}, {%0,%1,%2,%3};"
        : "+f"(d0), "+f"(d1), "+f"(d2), "+f"(d3)
        : "r"(a0), "r"(a1), "r"(a2), "r"(a3), "r"(b0), "r"(b1));
}

// ---- K0: b-invariant precompute ----
__global__ void k0_kernel(const int* __restrict__ iidx, const float* __restrict__ item_b,
                          const float* __restrict__ aw1,
                          const float* __restrict__ bn_gamma, const float* __restrict__ bn_beta,
                          const float* __restrict__ bn_mean, const float* __restrict__ bn_var,
                          const float* __restrict__ w1, const float* __restrict__ b1) {
    int blk = blockIdx.x, tid = threadIdx.x;
    if (blk < 8) {
        int c = blk * 256 + tid;
        g_ibg[c] = item_b[iidx[c]];
    } else if (blk == 8) {
        for (int e = tid; e < 1024; e += 256) {
            int j = e >> 6, kp = e & 63;
            int k0 = 2 * kp, k1 = k0 + 1;
            float d0 = aw1[(128 + k0) * 16 + j] - aw1[(256 + k0) * 16 + j];
            float d1 = aw1[(128 + k1) * 16 + j] - aw1[(256 + k1) * 16 + j];
            g_DP[e] = pack2(d0, d1);
            g_AP[e] = pack2(aw1[(384 + k0) * 16 + j], aw1[(384 + k1) * 16 + j]);
        }
    } else if (blk == 9) {
        for (int idx = tid; idx < 2048; idx += 256) {
            int k = idx >> 4, j = idx & 15;
            g_S[idx] = aw1[k * 16 + j] + aw1[(256 + k) * 16 + j];
        }
    } else if (blk == 10) {
        for (int idx = tid; idx < 4096; idx += 256) {
            int d = idx >> 4;
            float g = bn_gamma[d] * rsqrtf(bn_var[d] + 1e-3f);
            g_w1g[idx] = w1[idx] * g;
        }
    } else {
        __shared__ float red[256];
        int j = tid & 15, ch = tid >> 4;
        float p = 0.0f;
        #pragma unroll
        for (int r = 0; r < 16; r++) {
            int d = ch * 16 + r;
            float g = bn_gamma[d] * rsqrtf(bn_var[d] + 1e-3f);
            float off = bn_beta[d] - bn_mean[d] * g;
            p = fmaf(off, w1[d * 16 + j], p);
        }
        red[ch * 16 + j] = p;
        __syncthreads();
        if (tid < 16) {
            float a = b1[tid];
            #pragma unroll
            for (int c2 = 0; c2 < 16; c2++) a += red[c2 * 16 + tid];
            g_b1p[tid] = a;
        }
    }
}

// h FIRST, wt immediately after: MMA A-tile rows 50..63 overflow into wt
// (read-only, finite, masked via e=0 — never stored).
struct Smem {
    float h[TC * 128];      // staged h chunk [t][k], col ^= (t&7)<<2
    float wt[16 * 128];     // W_eff [j][k],  col ^= (j&7)<<2
    unsigned long long r8[256];
    float q[128];
    float cb[16];
    float sc[200];          // exp(score), pre-zeroed
    float redf[256];
    float aw2s[128];
    float ab2s[8], aw3s[8], misc[8];
    float s1[16], s2[8];
    int   hid[200];
};

__global__ void __launch_bounds__(256, 4) din_main(
    const int* __restrict__ iidx, const int* __restrict__ hist_i,
    const int* __restrict__ sl, const int* __restrict__ category_list,
    const float* __restrict__ item_emb, const float* __restrict__ cat_emb,
    const float* __restrict__ ab1,
    const float* __restrict__ aw2, const float* __restrict__ ab2,
    const float* __restrict__ aw3, const float* __restrict__ ab3,
    const float* __restrict__ aw4, const float* __restrict__ ab4,
    const float* __restrict__ w2, const float* __restrict__ b2,
    const float* __restrict__ w3, const float* __restrict__ b3,
    float* __restrict__ out)
{
    extern __shared__ char smraw[];
    Smem& s = *reinterpret_cast<Smem*>(smraw);

    const int b    = blockIdx.x;
    const int tid  = threadIdx.x;
    const int warp = tid >> 5, lane = tid & 31;

    const int ib   = iidx[b];
    const int icat = category_list[ib];
    const int slb  = sl[b];

    // ---- phase 0 ----
    if (tid < 128) s.q[tid] = (tid < 64) ? item_emb[(size_t)ib * EE + tid]
                                         : cat_emb[(size_t)icat * EE + (tid - 64)];
    if (tid < 200) { s.hid[tid] = hist_i[b * TT + tid]; s.sc[tid] = 0.0f; }
    if (tid < 128) s.aw2s[tid] = aw2[tid];
    if (tid < 8) { s.ab2s[tid] = ab2[tid]; s.aw3s[tid] = aw3[tid]; }
    if (tid == 0) s.misc[0] = ab3[0];
    __syncthreads();

    // ---- phase 1: W_eff -> wt[j][k] (swizzled) + cb ----
    #pragma unroll
    for (int e = tid; e < 1024; e += 256) {
        int j = e >> 6, kp = e & 63;
        unsigned long long qp = *(const unsigned long long*)(s.q + 2 * kp);
        unsigned long long d  = g_DP[e];
        ffma2(d, qp, g_AP[e]);
        int col = (2 * kp) ^ ((j & 7) << 2);
        *(unsigned long long*)(s.wt + j * 128 + col) = d;
    }
    {
        int j = tid & 15, ch = tid >> 4;
        float p = 0.0f;
        #pragma unroll
        for (int r = 0; r < 8; r++) {
            int k = ch * 8 + r;
            p = fmaf(s.q[k], g_S[k * 16 + j], p);
        }
        s.redf[ch * 16 + j] = p;
    }
    __syncthreads();
    if (tid < 16) {
        float a = ab1[tid];
        #pragma unroll
        for (int ch = 0; ch < 16; ch++) a += s.redf[ch * 16 + tid];
        s.cb[tid] = a;
    }
    __syncthreads();

    unsigned long long acc2 = 0;
    const int kpw = tid & 63, q4 = tid >> 6;

    #pragma unroll 1
    for (int c = 0; c < 4; c++) {
        const int tbase = c * TC;
        if (tbase >= slb) break;                 // slb block-uniform -> legal
        const int rem = min(TC, slb - tbase);

        // stage only active rows (coalesced warp-per-row)
        for (int r = warp; r < 2 * rem; r += 8) {
            int tl = r >> 1, table = r & 1;
            int hd = s.hid[tbase + tl];
            const float* src = table ? cat_emb : item_emb;
            unsigned long long v =
                *(const unsigned long long*)(src + (size_t)hd * EE + 2 * lane);
            int col = (table * 64 + 2 * lane) ^ ((tl & 7) << 2);
            *(unsigned long long*)(s.h + tl * 128 + col) = v;
        }
        __syncthreads();

        // mma + in-register sigmoid MLP (warps 0..3, rows warp*16..+15)
        if (warp < 4 && warp * 16 < rem) {
            int g = lane >> 2, qd = lane & 3;
            int trowA = warp * 16 + g, trowB = trowA + 8;
            int xsw = g << 2;
            const float* hA0 = s.h + trowA * 128;
            const float* hA1 = s.h + trowB * 128;
            const float* bB  = s.wt + g * 128;
            float d00 = 0.f, d01 = 0.f, d02 = 0.f, d03 = 0.f;
            float d10 = 0.f, d11 = 0.f, d12 = 0.f, d13 = 0.f;
            #pragma unroll
            for (int ks = 0; ks < 16; ks++) {
                int c1 = (8 * ks + qd) ^ xsw;
                int c2 = c1 ^ 4;
                unsigned a0 = __float_as_uint(hA0[c1]);
                unsigned a1 = __float_as_uint(hA1[c1]);
                unsigned a2 = __float_as_uint(hA0[c2]);
                unsigned a3 = __float_as_uint(hA1[c2]);
                unsigned b0 = __float_as_uint(bB[c1]);
                unsigned b1 = __float_as_uint(bB[c2]);
                unsigned b2v = __float_as_uint(bB[8 * 128 + c1]);
                unsigned b3v = __float_as_uint(bB[8 * 128 + c2]);
                mma_tf32(d00, d01, d02, d03, a0, a1, a2, a3, b0, b1);
                mma_tf32(d10, d11, d12, d13, a0, a1, a2, a3, b2v, b3v);
            }
            // lane owns j = {2qd, 2qd+1, 8+2qd, 9+2qd} for rows trowA, trowB
            int j0 = 2 * qd, j1 = j0 + 1, j2 = j0 + 8, j3 = j0 + 9;
            float cb0 = s.cb[j0], cb1 = s.cb[j1], cb2 = s.cb[j2], cb3 = s.cb[j3];
            float xA0 = sigmoid_fast(d00 + cb0), xA1 = sigmoid_fast(d01 + cb1);
            float xA2 = sigmoid_fast(d10 + cb2), xA3 = sigmoid_fast(d11 + cb3);
            float xB0 = sigmoid_fast(d02 + cb0), xB1 = sigmoid_fast(d03 + cb1);
            float xB2 = sigmoid_fast(d12 + cb2), xB3 = sigmoid_fast(d13 + cb3);
            float yA[8], yB[8];
            #pragma unroll
            for (int o = 0; o < 8; o++) {
                float w0 = s.aw2s[j0 * 8 + o], w1v = s.aw2s[j1 * 8 + o];
                float w2v = s.aw2s[j2 * 8 + o], w3v = s.aw2s[j3 * 8 + o];
                yA[o] = fmaf(xA0, w0, fmaf(xA1, w1v, fmaf(xA2, w2v, xA3 * w3v)));
                yB[o] = fmaf(xB0, w0, fmaf(xB1, w1v, fmaf(xB2, w2v, xB3 * w3v)));
            }
            #pragma unroll
            for (int o = 0; o < 8; o++) {
                yA[o] += __shfl_xor_sync(0xffffffffu, yA[o], 1);
                yA[o] += __shfl_xor_sync(0xffffffffu, yA[o], 2);
                yB[o] += __shfl_xor_sync(0xffffffffu, yB[o], 1);
                yB[o] += __shfl_xor_sync(0xffffffffu, yB[o], 2);
            }
            int oa = 2 * qd, ob = oa + 1;
            float a2a = s.ab2s[oa], a2b = s.ab2s[ob];
            float a3a = s.aw3s[oa], a3b = s.aw3s[ob];
            float pA = fmaf(sigmoid_fast(yA[oa] + a2a), a3a,
                            sigmoid_fast(yA[ob] + a2b) * a3b);
            float pB = fmaf(sigmoid_fast(yB[oa] + a2a), a3a,
                            sigmoid_fast(yB[ob] + a2b) * a3b);
            pA += __shfl_xor_sync(0xffffffffu, pA, 1);
            pA += __shfl_xor_sync(0xffffffffu, pA, 2);
            pB += __shfl_xor_sync(0xffffffffu, pB, 1);
            pB += __shfl_xor_sync(0xffffffffu, pB, 2);
            if (qd == 0) {
                float ab3v = s.misc[0];
                if (trowA < TC) {
                    int tg = tbase + trowA;
                    s.sc[tg] = (tg < slb)
                        ? __expf((pA + ab3v) * 0.08838834764831844f) : 0.0f;
                }
                if (trowB < TC) {
                    int tg = tbase + trowB;
                    s.sc[tg] = (tg < slb)
                        ? __expf((pB + ab3v) * 0.08838834764831844f) : 0.0f;
                }
            }
        }
        __syncthreads();

        // streamed weighted sum over active rows
        for (int tl = q4; tl < rem; tl += 4) {
            float ev = s.sc[tbase + tl];
            int col = (2 * kpw) ^ ((tl & 7) << 2);
            unsigned long long hv = *(const unsigned long long*)(s.h + tl * 128 + col);
            ffma2(acc2, pack2(ev, ev), hv);
        }
        __syncthreads();
    }
    s.r8[tid] = acc2;
    __syncthreads();

    // Z
    if (tid < 32) {
        float z = 0.0f;
        for (int t = tid; t < TT; t += 32) z += s.sc[t];
        #pragma unroll
        for (int o = 16; o; o >>= 1) z += __shfl_xor_sync(0xffffffffu, z, o);
        if (tid == 0) s.misc[2] = 1.0f / z;
    }
    __syncthreads();

    // h1
    if (tid < 64) {
        float iz = s.misc[2];
        float lo0, hi0, lo1, hi1, lo2, hi2, lo3, hi3;
        unpack2(s.r8[tid],       lo0, hi0);
        unpack2(s.r8[64 + tid],  lo1, hi1);
        unpack2(s.r8[128 + tid], lo2, hi2);
        unpack2(s.r8[192 + tid], lo3, hi3);
        s.redf[2 * tid]     = (lo0 + lo1 + lo2 + lo3) * iz;
        s.redf[2 * tid + 1] = (hi0 + hi1 + hi2 + hi3) * iz;
    }
    __syncthreads();

    // h2 = h1 @ aw4 (split-k by 2)
    {
        int col = tid & 127, hf = tid >> 7;
        float a = 0.0f;
        int k0 = hf * 64;
        #pragma unroll 4
        for (int k = k0; k < k0 + 64; k++)
            a = fmaf(s.redf[k], aw4[k * 128 + col], a);
        ((float*)s.r8)[hf * 128 + col] = a;
    }
    __syncthreads();

    // head MLP, BN folded
    {
        int j = tid & 15, ch = tid >> 4;
        const float* r8f = (const float*)s.r8;
        float p = 0.0f;
        #pragma unroll
        for (int r = 0; r < 16; r++) {
            int d = ch * 16 + r;
            float v = (d < 128) ? (r8f[d] + r8f[128 + d] + ab4[d]) : s.q[d - 128];
            p = fmaf(v, g_w1g[d * 16 + j], p);
        }
        s.redf[ch * 16 + j] = p;
    }
    __syncthreads();
    if (tid < 16) {
        float a = g_b1p[tid];
        #pragma unroll
        for (int ch = 0; ch < 16; ch++) a += s.redf[ch * 16 + tid];
        s.s1[tid] = a;
    }
    __syncthreads();
    if (tid < 8) {
        float a = b2[tid];
        #pragma unroll
        for (int j = 0; j < 16; j++) a = fmaf(s.s1[j], w2[j * 8 + tid], a);
        s.s2[tid] = a;
    }
    __syncthreads();
    if (tid == 0) {
        float a = b3[0];
        #pragma unroll
        for (int o = 0; o < 8; o++) a = fmaf(s.s2[o], w3[o], a);
        s.misc[3] = a;
    }
    __syncthreads();

    // fused output row
    float s3 = s.misc[3];
    const float4* g4 = (const float4*)g_ibg;
    float4* o4 = (float4*)(out + (size_t)b * BB);
    #pragma unroll
    for (int c4 = tid; c4 < BB / 4; c4 += 256) {
        float4 v = g4[c4];
        v.x += s3; v.y += s3; v.z += s3; v.w += s3;
        o4[c4] = v;
    }
}

extern "C" void kernel_launch(void* const* d_in, const int* in_sizes, int n_in,
                              void* d_out, int out_size) {
    const int*   i_arr   = (const int*)d_in[1];
    const int*   hist_i  = (const int*)d_in[2];
    const int*   sl      = (const int*)d_in[3];
    const int*   catlist = (const int*)d_in[4];
    const float* item_emb = (const float*)d_in[5];
    const float* cat_emb  = (const float*)d_in[6];
    const float* item_b   = (const float*)d_in[7];
    const float* aw1 = (const float*)d_in[8];
    const float* ab1 = (const float*)d_in[9];
    const float* aw2 = (const float*)d_in[10];
    const float* ab2 = (const float*)d_in[11];
    const float* aw3 = (const float*)d_in[12];
    const float* ab3 = (const float*)d_in[13];
    const float* aw4 = (const float*)d_in[14];
    const float* ab4 = (const float*)d_in[15];
    const float* bn_gamma = (const float*)d_in[16];
    const float* bn_beta  = (const float*)d_in[17];
    const float* bn_mean  = (const float*)d_in[18];
    const float* bn_var   = (const float*)d_in[19];
    const float* w1 = (const float*)d_in[20];
    const float* b1 = (const float*)d_in[21];
    const float* w2 = (const float*)d_in[22];
    const float* b2 = (const float*)d_in[23];
    const float* w3 = (const float*)d_in[24];
    const float* b3 = (const float*)d_in[25];
    float* out = (float*)d_out;

    static int smem_set = 0;
    if (!smem_set) {
        cudaFuncSetAttribute(din_main, cudaFuncAttributeMaxDynamicSharedMemorySize,
                             (int)sizeof(Smem));
        smem_set = 1;
    }

    k0_kernel<<<12, 256>>>(i_arr, item_b, aw1, bn_gamma, bn_beta, bn_mean, bn_var,
                           w1, b1);
    din_main<<<BB, 256, sizeof(Smem)>>>(
        i_arr, hist_i, sl, catlist, item_emb, cat_emb,
        ab1, aw2, ab2, aw3, ab3, aw4, ab4,
        w2, b2, w3, b3, out);
}

// round 7
// speedup vs baseline: 3.5837x; 1.1448x over previous
#include <cuda_runtime.h>
#include <cuda_bf16.h>
#include <math.h>

#define BB 2048
#define TT 200
#define EE 64
#define TC 50

// ---- persistent device scratch (b-invariant precompute) ----
__device__ float              g_ibg[BB];      // item_b[i[c]]
__device__ unsigned long long g_DP[1024];     // (A2-A3) pairs, [j*64+kp]
__device__ unsigned long long g_AP[1024];     // A4(att) pairs, [j*64+kp]
__device__ float              g_S[2048];      // A1+A3          [k*16+j]
__device__ float              g_u[128];       // aw4 @ wv[0:128]
__device__ float              g_wvq[128];     // wv[128:256]
__device__ float              g_C[1];         // collapsed constant

__device__ __forceinline__ void ffma2(unsigned long long& d,
                                      unsigned long long a,
                                      unsigned long long b) {
    asm("fma.rn.f32x2 %0, %1, %2, %0;" : "+l"(d) : "l"(a), "l"(b));
}
__device__ __forceinline__ unsigned long long pack2(float lo, float hi) {
    unsigned long long r;
    asm("mov.b64 %0, {%1, %2};" : "=l"(r) : "f"(lo), "f"(hi));
    return r;
}
__device__ __forceinline__ void unpack2(unsigned long long v, float& lo, float& hi) {
    asm("mov.b64 {%0, %1}, %2;" : "=f"(lo), "=f"(hi) : "l"(v));
}

__device__ __forceinline__ float sigmoid_fast(float x) {
    float e;
    asm("ex2.approx.f32 %0, %1;" : "=f"(e) : "f"(x * -1.4426950408889634f));
    float d = 1.0f + e, r;
    asm("rcp.approx.f32 %0, %1;" : "=f"(r) : "f"(d));
    return r;
}

__device__ __forceinline__ void mma_tf32(float& d0, float& d1, float& d2, float& d3,
                                         unsigned a0, unsigned a1, unsigned a2, unsigned a3,
                                         unsigned b0, unsigned b1) {
    asm volatile(
        "mma.sync.aligned.m16n8k8.row.col.f32.tf32.tf32.f32 "
        "{%0,%1,%2,%3}, {%4,%5,%6,%7}, {%8,%9}, {%0,%1,%2,%3};"
        : "+f"(d0), "+f"(d1), "+f"(d2), "+f"(d3)
        : "r"(a0), "r"(a1), "r"(a2), "r"(a3), "r"(b0), "r"(b1));
}

// ---- K0: b-invariant precompute (incl. full linear-head collapse) ----
__global__ void k0_kernel(const int* __restrict__ iidx, const float* __restrict__ item_b,
                          const float* __restrict__ aw1,
                          const float* __restrict__ aw4, const float* __restrict__ ab4,
                          const float* __restrict__ bn_gamma, const float* __restrict__ bn_beta,
                          const float* __restrict__ bn_mean, const float* __restrict__ bn_var,
                          const float* __restrict__ w1, const float* __restrict__ b1,
                          const float* __restrict__ w2, const float* __restrict__ b2,
                          const float* __restrict__ w3, const float* __restrict__ b3) {
    int blk = blockIdx.x, tid = threadIdx.x;
    if (blk < 8) {
        int c = blk * 256 + tid;
        g_ibg[c] = item_b[iidx[c]];
    } else if (blk == 8) {
        for (int e = tid; e < 1024; e += 256) {
            int j = e >> 6, kp = e & 63;
            int k0 = 2 * kp, k1 = k0 + 1;
            float d0 = aw1[(128 + k0) * 16 + j] - aw1[(256 + k0) * 16 + j];
            float d1 = aw1[(128 + k1) * 16 + j] - aw1[(256 + k1) * 16 + j];
            g_DP[e] = pack2(d0, d1);
            g_AP[e] = pack2(aw1[(384 + k0) * 16 + j], aw1[(384 + k1) * 16 + j]);
        }
    } else if (blk == 9) {
        for (int idx = tid; idx < 2048; idx += 256) {
            int k = idx >> 4, j = idx & 15;
            g_S[idx] = aw1[k * 16 + j] + aw1[(256 + k) * 16 + j];
        }
    } else {
        // linear-head collapse:
        //   v2 = w2 @ w3 ; wsum_d = w1[d,:]·v2 ; g_d = gamma/sqrt(var+eps)
        //   wv_d = g_d*wsum_d ; off_d = beta - mean*g_d
        //   C = Σ off_d*wsum_d + b1·v2 + b2·w3 + b3 + Σ_{d<128} ab4_d*wv_d
        //   u_k = Σ_{d<128} aw4[k,d]*wv_d ; wvq = wv[128:256]
        __shared__ float wv[256];
        __shared__ float redC[256];
        int d = tid;
        float v2[16];
        #pragma unroll
        for (int j = 0; j < 16; j++) {
            float a = 0.0f;
            #pragma unroll
            for (int o = 0; o < 8; o++) a = fmaf(w2[j * 8 + o], w3[o], a);
            v2[j] = a;
        }
        float wsum = 0.0f;
        #pragma unroll
        for (int j = 0; j < 16; j++) wsum = fmaf(w1[d * 16 + j], v2[j], wsum);
        float g   = bn_gamma[d] * rsqrtf(bn_var[d] + 1e-3f);
        float wvd = g * wsum;
        wv[d] = wvd;
        float off = bn_beta[d] - bn_mean[d] * g;
        float pc  = off * wsum;
        if (d < 128) pc = fmaf(ab4[d], wvd, pc);
        if (d == 0) {
            float c = b3[0];
            #pragma unroll
            for (int o = 0; o < 8; o++) c = fmaf(b2[o], w3[o], c);
            #pragma unroll
            for (int j = 0; j < 16; j++) c = fmaf(b1[j], v2[j], c);
            pc += c;
        }
        redC[d] = pc;
        __syncthreads();
        if (tid < 128) redC[tid] += redC[tid + 128];
        __syncthreads();
        if (tid < 64) redC[tid] += redC[tid + 64];
        __syncthreads();
        if (tid < 32) {
            float c = redC[tid] + redC[tid + 32];
            #pragma unroll
            for (int o = 16; o; o >>= 1) c += __shfl_xor_sync(0xffffffffu, c, o);
            if (tid == 0) g_C[0] = c;
        }
        if (tid < 128) {
            float a = 0.0f;
            #pragma unroll 4
            for (int dd = 0; dd < 128; dd++) a = fmaf(aw4[tid * 128 + dd], wv[dd], a);
            g_u[tid] = a;
        } else {
            g_wvq[tid - 128] = wv[tid];
        }
    }
}

// h FIRST, wt immediately after: MMA A-tile rows 50..63 overflow into wt
// (read-only, finite, masked via e=0 — never stored).
struct Smem {
    float h[TC * 128];      // staged h chunk [t][k], col ^= (t&7)<<2
    float wt[16 * 128];     // W_eff [j][k],  col ^= (j&7)<<2
    unsigned long long r8[256];
    float q[128];
    float cb[16];
    float sc[200];          // exp(score), pre-zeroed
    float redf[256];
    float aw2s[128];
    float ab2s[8], aw3s[8], misc[8];
    int   hid[200];
};

__global__ void __launch_bounds__(256, 4) din_main(
    const int* __restrict__ iidx, const int* __restrict__ hist_i,
    const int* __restrict__ sl, const int* __restrict__ category_list,
    const float* __restrict__ item_emb, const float* __restrict__ cat_emb,
    const float* __restrict__ ab1,
    const float* __restrict__ aw2, const float* __restrict__ ab2,
    const float* __restrict__ aw3, const float* __restrict__ ab3,
    float* __restrict__ out)
{
    extern __shared__ char smraw[];
    Smem& s = *reinterpret_cast<Smem*>(smraw);

    const int b    = blockIdx.x;
    const int tid  = threadIdx.x;
    const int warp = tid >> 5, lane = tid & 31;

    const int ib   = iidx[b];
    const int icat = category_list[ib];
    const int slb  = sl[b];

    // ---- phase 0 ----
    if (tid < 128) s.q[tid] = (tid < 64) ? item_emb[(size_t)ib * EE + tid]
                                         : cat_emb[(size_t)icat * EE + (tid - 64)];
    if (tid < 200) { s.hid[tid] = hist_i[b * TT + tid]; s.sc[tid] = 0.0f; }
    if (tid < 128) s.aw2s[tid] = aw2[tid];
    if (tid < 8) { s.ab2s[tid] = ab2[tid]; s.aw3s[tid] = aw3[tid]; }
    if (tid == 0) s.misc[0] = ab3[0];
    __syncthreads();

    // ---- phase 1: W_eff -> wt[j][k] (swizzled) + cb ----
    #pragma unroll
    for (int e = tid; e < 1024; e += 256) {
        int j = e >> 6, kp = e & 63;
        unsigned long long qp = *(const unsigned long long*)(s.q + 2 * kp);
        unsigned long long d  = g_DP[e];
        ffma2(d, qp, g_AP[e]);
        int col = (2 * kp) ^ ((j & 7) << 2);
        *(unsigned long long*)(s.wt + j * 128 + col) = d;
    }
    {
        int j = tid & 15, ch = tid >> 4;
        float p = 0.0f;
        #pragma unroll
        for (int r = 0; r < 8; r++) {
            int k = ch * 8 + r;
            p = fmaf(s.q[k], g_S[k * 16 + j], p);
        }
        s.redf[ch * 16 + j] = p;
    }
    __syncthreads();
    if (tid < 16) {
        float a = ab1[tid];
        #pragma unroll
        for (int ch = 0; ch < 16; ch++) a += s.redf[ch * 16 + tid];
        s.cb[tid] = a;
    }
    __syncthreads();

    unsigned long long acc2 = 0;
    const int kpw = tid & 63, q4 = tid >> 6;

    #pragma unroll 1
    for (int c = 0; c < 4; c++) {
        const int tbase = c * TC;
        if (tbase >= slb) break;                 // slb block-uniform -> legal
        const int rem = min(TC, slb - tbase);

        // stage only active rows (coalesced warp-per-row)
        for (int r = warp; r < 2 * rem; r += 8) {
            int tl = r >> 1, table = r & 1;
            int hd = s.hid[tbase + tl];
            const float* src = table ? cat_emb : item_emb;
            unsigned long long v =
                *(const unsigned long long*)(src + (size_t)hd * EE + 2 * lane);
            int col = (table * 64 + 2 * lane) ^ ((tl & 7) << 2);
            *(unsigned long long*)(s.h + tl * 128 + col) = v;
        }
        __syncthreads();

        // mma + in-register sigmoid MLP (warps 0..3, rows warp*16..+15)
        if (warp < 4 && warp * 16 < rem) {
            int g = lane >> 2, qd = lane & 3;
            int trowA = warp * 16 + g, trowB = trowA + 8;
            int xsw = g << 2;
            const float* hA0 = s.h + trowA * 128;
            const float* hA1 = s.h + trowB * 128;
            const float* bB  = s.wt + g * 128;
            float d00 = 0.f, d01 = 0.f, d02 = 0.f, d03 = 0.f;
            float d10 = 0.f, d11 = 0.f, d12 = 0.f, d13 = 0.f;
            #pragma unroll
            for (int ks = 0; ks < 16; ks++) {
                int c1 = (8 * ks + qd) ^ xsw;
                int c2 = c1 ^ 4;
                unsigned a0 = __float_as_uint(hA0[c1]);
                unsigned a1 = __float_as_uint(hA1[c1]);
                unsigned a2 = __float_as_uint(hA0[c2]);
                unsigned a3 = __float_as_uint(hA1[c2]);
                unsigned b0 = __float_as_uint(bB[c1]);
                unsigned b1 = __float_as_uint(bB[c2]);
                unsigned b2v = __float_as_uint(bB[8 * 128 + c1]);
                unsigned b3v = __float_as_uint(bB[8 * 128 + c2]);
                mma_tf32(d00, d01, d02, d03, a0, a1, a2, a3, b0, b1);
                mma_tf32(d10, d11, d12, d13, a0, a1, a2, a3, b2v, b3v);
            }
            int j0 = 2 * qd, j1 = j0 + 1, j2 = j0 + 8, j3 = j0 + 9;
            float cb0 = s.cb[j0], cb1 = s.cb[j1], cb2 = s.cb[j2], cb3 = s.cb[j3];
            float xA0 = sigmoid_fast(d00 + cb0), xA1 = sigmoid_fast(d01 + cb1);
            float xA2 = sigmoid_fast(d10 + cb2), xA3 = sigmoid_fast(d11 + cb3);
            float xB0 = sigmoid_fast(d02 + cb0), xB1 = sigmoid_fast(d03 + cb1);
            float xB2 = sigmoid_fast(d12 + cb2), xB3 = sigmoid_fast(d13 + cb3);
            float yA[8], yB[8];
            #pragma unroll
            for (int o = 0; o < 8; o++) {
                float w0 = s.aw2s[j0 * 8 + o], w1v = s.aw2s[j1 * 8 + o];
                float w2v = s.aw2s[j2 * 8 + o], w3v = s.aw2s[j3 * 8 + o];
                yA[o] = fmaf(xA0, w0, fmaf(xA1, w1v, fmaf(xA2, w2v, xA3 * w3v)));
                yB[o] = fmaf(xB0, w0, fmaf(xB1, w1v, fmaf(xB2, w2v, xB3 * w3v)));
            }
            #pragma unroll
            for (int o = 0; o < 8; o++) {
                yA[o] += __shfl_xor_sync(0xffffffffu, yA[o], 1);
                yA[o] += __shfl_xor_sync(0xffffffffu, yA[o], 2);
                yB[o] += __shfl_xor_sync(0xffffffffu, yB[o], 1);
                yB[o] += __shfl_xor_sync(0xffffffffu, yB[o], 2);
            }
            int oa = 2 * qd, ob = oa + 1;
            float a2a = s.ab2s[oa], a2b = s.ab2s[ob];
            float a3a = s.aw3s[oa], a3b = s.aw3s[ob];
            float pA = fmaf(sigmoid_fast(yA[oa] + a2a), a3a,
                            sigmoid_fast(yA[ob] + a2b) * a3b);
            float pB = fmaf(sigmoid_fast(yB[oa] + a2a), a3a,
                            sigmoid_fast(yB[ob] + a2b) * a3b);
            pA += __shfl_xor_sync(0xffffffffu, pA, 1);
            pA += __shfl_xor_sync(0xffffffffu, pA, 2);
            pB += __shfl_xor_sync(0xffffffffu, pB, 1);
            pB += __shfl_xor_sync(0xffffffffu, pB, 2);
            if (qd == 0) {
                float ab3v = s.misc[0];
                if (trowA < TC) {
                    int tg = tbase + trowA;
                    s.sc[tg] = (tg < slb)
                        ? __expf((pA + ab3v) * 0.08838834764831844f) : 0.0f;
                }
                if (trowB < TC) {
                    int tg = tbase + trowB;
                    s.sc[tg] = (tg < slb)
                        ? __expf((pB + ab3v) * 0.08838834764831844f) : 0.0f;
                }
            }
        }
        __syncthreads();

        // streamed weighted sum over active rows
        for (int tl = q4; tl < rem; tl += 4) {
            float ev = s.sc[tbase + tl];
            int col = (2 * kpw) ^ ((tl & 7) << 2);
            unsigned long long hv = *(const unsigned long long*)(s.h + tl * 128 + col);
            ffma2(acc2, pack2(ev, ev), hv);
        }
        __syncthreads();
    }
    s.r8[tid] = acc2;
    __syncthreads();

    // ---- collapsed epilogue: scalar = (raw_h·u)/Z + q·wvq + C ----
    // warps 0-1: raw_h·u ; warps 2-5: q·wvq ; warps 6-7: Z
    float part = 0.0f;
    if (warp < 2) {
        int t = tid;                       // 0..63, k-pair index
        float lo0, hi0, lo1, hi1, lo2, hi2, lo3, hi3;
        unpack2(s.r8[t],       lo0, hi0);
        unpack2(s.r8[64 + t],  lo1, hi1);
        unpack2(s.r8[128 + t], lo2, hi2);
        unpack2(s.r8[192 + t], lo3, hi3);
        float k0v = lo0 + lo1 + lo2 + lo3;
        float k1v = hi0 + hi1 + hi2 + hi3;
        part = fmaf(k0v, g_u[2 * t], k1v * g_u[2 * t + 1]);
    } else if (warp < 6) {
        int d = tid - 64;                  // 0..127
        part = s.q[d] * g_wvq[d];
    } else {
        for (int t = tid - 192; t < TT; t += 64) part += s.sc[t];
    }
    #pragma unroll
    for (int o = 16; o; o >>= 1) part += __shfl_xor_sync(0xffffffffu, part, o);
    if (lane == 0) s.redf[warp] = part;
    __syncthreads();
    if (tid == 0) {
        float S1 = s.redf[0] + s.redf[1];
        float S2 = s.redf[2] + s.redf[3] + s.redf[4] + s.redf[5];
        float Z  = s.redf[6] + s.redf[7];
        s.misc[3] = S1 / Z + S2 + g_C[0];
    }
    __syncthreads();

    // fused output row
    float s3 = s.misc[3];
    const float4* g4 = (const float4*)g_ibg;
    float4* o4 = (float4*)(out + (size_t)b * BB);
    #pragma unroll
    for (int c4 = tid; c4 < BB / 4; c4 += 256) {
        float4 v = g4[c4];
        v.x += s3; v.y += s3; v.z += s3; v.w += s3;
        o4[c4] = v;
    }
}

extern "C" void kernel_launch(void* const* d_in, const int* in_sizes, int n_in,
                              void* d_out, int out_size) {
    const int*   i_arr   = (const int*)d_in[1];
    const int*   hist_i  = (const int*)d_in[2];
    const int*   sl      = (const int*)d_in[3];
    const int*   catlist = (const int*)d_in[4];
    const float* item_emb = (const float*)d_in[5];
    const float* cat_emb  = (const float*)d_in[6];
    const float* item_b   = (const float*)d_in[7];
    const float* aw1 = (const float*)d_in[8];
    const float* ab1 = (const float*)d_in[9];
    const float* aw2 = (const float*)d_in[10];
    const float* ab2 = (const float*)d_in[11];
    const float* aw3 = (const float*)d_in[12];
    const float* ab3 = (const float*)d_in[13];
    const float* aw4 = (const float*)d_in[14];
    const float* ab4 = (const float*)d_in[15];
    const float* bn_gamma = (const float*)d_in[16];
    const float* bn_beta  = (const float*)d_in[17];
    const float* bn_mean  = (const float*)d_in[18];
    const float* bn_var   = (const float*)d_in[19];
    const float* w1 = (const float*)d_in[20];
    const float* b1 = (const float*)d_in[21];
    const float* w2 = (const float*)d_in[22];
    const float* b2 = (const float*)d_in[23];
    const float* w3 = (const float*)d_in[24];
    const float* b3 = (const float*)d_in[25];
    float* out = (float*)d_out;

    static int smem_set = 0;
    if (!smem_set) {
        cudaFuncSetAttribute(din_main, cudaFuncAttributeMaxDynamicSharedMemorySize,
                             (int)sizeof(Smem));
        smem_set = 1;
    }

    k0_kernel<<<11, 256>>>(i_arr, item_b, aw1, aw4, ab4,
                           bn_gamma, bn_beta, bn_mean, bn_var,
                           w1, b1, w2, b2, w3, b3);
    din_main<<<BB, 256, sizeof(Smem)>>>(
        i_arr, hist_i, sl, catlist, item_emb, cat_emb,
        ab1, aw2, ab2, aw3, ab3, out);
}